// round 10
// baseline (speedup 1.0000x reference)
#include <cuda_runtime.h>
#include <cstdint>

#define B_  8
#define S_  1024
#define D_  1024
#define H_  16
#define F_  64
#define HF_ 1024
#define EPS_ 1e-3f

// ---------------- scratch ----------------
__device__ float g_q[B_ * S_ * HF_];     // NOTE: q,k stored with k-dim 8-group interleave [0,4,1,5,2,6,3,7]
__device__ float g_k[B_ * S_ * HF_];
__device__ float g_v[B_ * S_ * HF_];     // natural layout
__device__ float g_enf[B_ * S_ * HF_];   // natural layout
__device__ float g_out2[B_ * S_ * F_];
__device__ float g_inv[B_ * HF_];
__device__ float g_weff[B_ * HF_ * F_];

// ---------------- tf32 mma.m16n8k8 ----------------
__device__ __forceinline__ void mma_tf32(float* d, const uint32_t* a, const uint32_t* b) {
    asm volatile(
        "mma.sync.aligned.m16n8k8.row.col.f32.tf32.tf32.f32 "
        "{%0,%1,%2,%3}, {%4,%5,%6,%7}, {%8,%9}, {%0,%1,%2,%3};\n"
        : "+f"(d[0]), "+f"(d[1]), "+f"(d[2]), "+f"(d[3])
        : "r"(a[0]), "r"(a[1]), "r"(a[2]), "r"(a[3]), "r"(b[0]), "r"(b[1]));
}

// ---------------- cp.async helpers ----------------
__device__ __forceinline__ void cpasync16(void* smem, const void* g) {
    uint32_t s = (uint32_t)__cvta_generic_to_shared(smem);
    asm volatile("cp.async.cg.shared.global [%0], [%1], 16;\n" :: "r"(s), "l"(g));
}
__device__ __forceinline__ void cpasync_commit() {
    asm volatile("cp.async.commit_group;\n" ::: "memory");
}
__device__ __forceinline__ void cpasync_wait0() {
    asm volatile("cp.async.wait_group 0;\n" ::: "memory");
}
__device__ __forceinline__ void cpasync_wait2() {
    asm volatile("cp.async.wait_group 2;\n" ::: "memory");
}

// ---------------- fast exp (FMA pipe) ----------------
__device__ __forceinline__ float fexp(float x) {
    float t = fmaxf(x * 1.4426950408889634f, -126.0f);
    int   i = __float2int_rn(t);
    float f = t - (float)i;
    float p = 0.0013333558146428443f;
    p = fmaf(p, f, 0.009618129842126066f);
    p = fmaf(p, f, 0.05550410866482158f);
    p = fmaf(p, f, 0.2402265069591007f);
    p = fmaf(p, f, 0.6931471805599453f);
    p = fmaf(p, f, 1.0f);
    return p * __int_as_float((i + 127) << 23);
}

// ---------------- merged QKV GEMM, 4-stage cp.async ring ----------------
// z<2 (q,k) outputs written with 8-group column interleave [0,4,1,5,2,6,3,7].
__global__ __launch_bounds__(256) void qkv_gemm(
    const float* __restrict__ A0, const float* __restrict__ A1, const float* __restrict__ A2,
    const float* __restrict__ W0, const float* __restrict__ W1p, const float* __restrict__ W2,
    const float* __restrict__ b0, const float* __restrict__ b1p, const float* __restrict__ b2,
    float* __restrict__ C0, float* __restrict__ C1, float* __restrict__ C2)
{
    extern __shared__ float gsm[];
    const int z = blockIdx.z;
    const float* A    = z == 0 ? A0 : (z == 1 ? A1 : A2);
    const float* W    = z == 0 ? W0 : (z == 1 ? W1p : W2);
    const float* bias = z == 0 ? b0 : (z == 1 ? b1p : b2);
    float*       C    = z == 0 ? C0 : (z == 1 ? C1 : C2);

    const int tid  = threadIdx.x;
    const int lane = tid & 31, warp = tid >> 5;
    const int wm   = warp & 1, wn = warp >> 1;
    const int m0   = blockIdx.y * 128;
    const int n0   = blockIdx.x * 128;

    float acc[4][4][4];
#pragma unroll
    for (int i = 0; i < 4; i++)
#pragma unroll
        for (int j = 0; j < 4; j++)
#pragma unroll
            for (int r = 0; r < 4; r++) acc[i][j][r] = 0.f;

    auto issue = [&](int k0, int stg) {
        float* As = gsm + stg * 4736;
        float* Ws = As + 2560;
#pragma unroll
        for (int t = 0; t < 2; t++) {
            int idx = tid + t * 256;
            int r = idx >> 2, c4 = idx & 3;
            cpasync16(&As[r * 20 + c4 * 4], &A[(size_t)(m0 + r) * D_ + k0 + c4 * 4]);
        }
#pragma unroll
        for (int t = 0; t < 2; t++) {
            int idx = tid + t * 256;
            int r = idx >> 5, c8 = idx & 31;
            cpasync16(&Ws[r * 136 + c8 * 4], &W[(size_t)(k0 + r) * HF_ + n0 + c8 * 4]);
        }
        cpasync_commit();
    };

    issue(0, 0);
    issue(16, 1);
    issue(32, 2);

    for (int it = 0; it < 64; it++) {
        cpasync_wait2();
        __syncthreads();
        if (it + 3 < 64) issue((it + 3) * 16, (it + 3) & 3);
        else cpasync_commit();

        const float* As = gsm + (it & 3) * 4736;
        const float* Ws = As + 2560;
#pragma unroll
        for (int kt = 0; kt < 2; kt++) {
            uint32_t af[4][4];
            const int ar = lane >> 2, ac = kt * 8 + (lane & 3);
#pragma unroll
            for (int mt = 0; mt < 4; mt++) {
                int rb = wm * 64 + mt * 16 + ar;
                af[mt][0] = __float_as_uint(As[rb * 20 + ac]);
                af[mt][1] = __float_as_uint(As[(rb + 8) * 20 + ac]);
                af[mt][2] = __float_as_uint(As[rb * 20 + ac + 4]);
                af[mt][3] = __float_as_uint(As[(rb + 8) * 20 + ac + 4]);
            }
            uint32_t bf[4][2];
#pragma unroll
            for (int nt = 0; nt < 4; nt++) {
                int bn = wn * 32 + nt * 8 + (lane >> 2);
                bf[nt][0] = __float_as_uint(Ws[(kt * 8 + (lane & 3)) * 136 + bn]);
                bf[nt][1] = __float_as_uint(Ws[(kt * 8 + (lane & 3) + 4) * 136 + bn]);
            }
#pragma unroll
            for (int mt = 0; mt < 4; mt++)
#pragma unroll
                for (int nt = 0; nt < 4; nt++)
                    mma_tf32(acc[mt][nt], af[mt], bf[nt]);
        }
    }

    const int l2 = (lane & 3) * 2;
    const int p0 = (l2 < 4) ? 2 * l2     : 2 * l2 - 7;   // pos(l2)
    const int p1 = (l2 < 4) ? 2 * l2 + 2 : 2 * l2 - 5;   // pos(l2+1)
#pragma unroll
    for (int mt = 0; mt < 4; mt++) {
#pragma unroll
        for (int nt = 0; nt < 4; nt++) {
            int r  = m0 + wm * 64 + mt * 16 + (lane >> 2);
            int cb = n0 + wn * 32 + nt * 8;
            float bv0 = bias[cb + l2], bv1 = bias[cb + l2 + 1];
            if (z == 2) {
                *(float2*)&C[(size_t)r * HF_ + cb + l2] =
                    make_float2(acc[mt][nt][0] + bv0, acc[mt][nt][1] + bv1);
                *(float2*)&C[(size_t)(r + 8) * HF_ + cb + l2] =
                    make_float2(acc[mt][nt][2] + bv0, acc[mt][nt][3] + bv1);
            } else {
                C[(size_t)r * HF_ + cb + p0]       = acc[mt][nt][0] + bv0;
                C[(size_t)r * HF_ + cb + p1]       = acc[mt][nt][1] + bv1;
                C[(size_t)(r + 8) * HF_ + cb + p0] = acc[mt][nt][2] + bv0;
                C[(size_t)(r + 8) * HF_ + cb + p1] = acc[mt][nt][3] + bv1;
            }
        }
    }
}

// ---------------- flash attention: 128-q tile, maxless softmax, paired LDS.64 frags ----------------
#define LD 68
__global__ __launch_bounds__(256, 2) void attn_tf32(
    const float* __restrict__ q, const float* __restrict__ k,
    const float* __restrict__ v, float* __restrict__ enf)
{
    extern __shared__ float sm[];
    float* Ks = sm;                    // [2][64*LD]  (k-interleaved cols)
    float* Vs = Ks + 2 * 64 * LD;      // [2][64*LD]  (natural)
    float* Ps = Vs + 2 * 64 * LD;      // [128*LD]    (Q staging, then P with j-interleaved cols)

    const int b = blockIdx.z, h = blockIdx.y, i0 = blockIdx.x * 128;
    const int tid = threadIdx.x, lane = tid & 31, warp = tid >> 5;
    const int r0 = warp * 16 + (lane >> 2), r1 = r0 + 8;
    const int lt = lane & 3;
    // P-store positions for natural cols 2lt, 2lt+1 under the 8-group interleave
    const int sp0 = (lt < 2) ? 4 * lt     : 4 * lt - 7;
    const int sp1 = (lt < 2) ? 4 * lt + 2 : 4 * lt - 5;

    auto issue = [&](int c0, int stg) {
        const float* kb = k + (size_t)(b * S_ + c0) * HF_ + h * 64;
        const float* vb = v + (size_t)(b * S_ + c0) * HF_ + h * 64;
        float* Kd = Ks + stg * 64 * LD;
        float* Vd = Vs + stg * 64 * LD;
#pragma unroll
        for (int t = 0; t < 4; t++) {
            int idx = tid + t * 256;
            int r = idx >> 4, c4 = idx & 15;
            cpasync16(&Kd[r * LD + c4 * 4], kb + (size_t)r * HF_ + c4 * 4);
            cpasync16(&Vd[r * LD + c4 * 4], vb + (size_t)r * HF_ + c4 * 4);
        }
        cpasync_commit();
    };

    issue(0, 0);

    // stage Q (pre-scaled; gmem already k-interleaved — copy verbatim)
    for (int idx = tid; idx < 128 * 16; idx += 256) {
        int r = idx >> 4, c4 = idx & 15;
        float4 vq = *(const float4*)&q[(size_t)(b * S_ + i0 + r) * HF_ + h * 64 + c4 * 4];
        vq.x *= 0.125f; vq.y *= 0.125f; vq.z *= 0.125f; vq.w *= 0.125f;
        *(float4*)&Ps[r * LD + c4 * 4] = vq;
    }
    __syncthreads();

    uint32_t qf[8][4];
#pragma unroll
    for (int kt = 0; kt < 8; kt++) {
        float2 t0 = *(const float2*)&Ps[r0 * LD + kt * 8 + 2 * lt];
        float2 t1 = *(const float2*)&Ps[r1 * LD + kt * 8 + 2 * lt];
        qf[kt][0] = __float_as_uint(t0.x);
        qf[kt][2] = __float_as_uint(t0.y);
        qf[kt][1] = __float_as_uint(t1.x);
        qf[kt][3] = __float_as_uint(t1.y);
    }

    float lrun0 = 0.f, lrun1 = 0.f;
    float oacc[8][4];
#pragma unroll
    for (int i = 0; i < 8; i++)
#pragma unroll
        for (int j = 0; j < 4; j++) oacc[i][j] = 0.f;

    for (int it = 0; it < 16; it++) {
        cpasync_wait0();
        __syncthreads();
        if (it < 15) issue((it + 1) * 64, (it + 1) & 1);

        const float* Kc = Ks + (it & 1) * 64 * LD;
        const float* Vc = Vs + (it & 1) * 64 * LD;

        // ---- S = (Q*0.125) K^T : K B-frag pairs via LDS.64 ----
        float sacc[8][4];
#pragma unroll
        for (int i = 0; i < 8; i++)
#pragma unroll
            for (int j = 0; j < 4; j++) sacc[i][j] = 0.f;
#pragma unroll
        for (int kt = 0; kt < 8; kt++) {
#pragma unroll
            for (int nt = 0; nt < 8; nt++) {
                int jn = nt * 8 + (lane >> 2);
                float2 kv = *(const float2*)&Kc[jn * LD + kt * 8 + 2 * lt];
                uint32_t bf[2] = { __float_as_uint(kv.x), __float_as_uint(kv.y) };
                mma_tf32(sacc[nt], qf[kt], bf);
            }
        }

        // ---- maxless softmax; store P with j-interleaved columns ----
        float sum0 = 0.f, sum1 = 0.f;
#pragma unroll
        for (int nt = 0; nt < 8; nt++) {
            float e0 = fexp(sacc[nt][0]);
            float e1 = fexp(sacc[nt][1]);
            float e2 = fexp(sacc[nt][2]);
            float e3 = fexp(sacc[nt][3]);
            sum0 += e0 + e1; sum1 += e2 + e3;
            Ps[r0 * LD + nt * 8 + sp0] = e0;
            Ps[r0 * LD + nt * 8 + sp1] = e1;
            Ps[r1 * LD + nt * 8 + sp0] = e2;
            Ps[r1 * LD + nt * 8 + sp1] = e3;
        }
        sum0 += __shfl_xor_sync(0xffffffffu, sum0, 1);
        sum0 += __shfl_xor_sync(0xffffffffu, sum0, 2);
        sum1 += __shfl_xor_sync(0xffffffffu, sum1, 1);
        sum1 += __shfl_xor_sync(0xffffffffu, sum1, 2);
        lrun0 += sum0;
        lrun1 += sum1;
        __syncwarp();

        // ---- O += P @ V : P A-frag pairs via LDS.64, V natural ----
#pragma unroll
        for (int kt = 0; kt < 8; kt++) {
            float2 a0 = *(const float2*)&Ps[r0 * LD + kt * 8 + 2 * lt];
            float2 a1 = *(const float2*)&Ps[r1 * LD + kt * 8 + 2 * lt];
            uint32_t af[4] = { __float_as_uint(a0.x), __float_as_uint(a1.x),
                               __float_as_uint(a0.y), __float_as_uint(a1.y) };
#pragma unroll
            for (int nt = 0; nt < 8; nt++) {
                uint32_t bf[2];
                int fn = nt * 8 + (lane >> 2);
                bf[0] = __float_as_uint(Vc[(kt * 8 + lt) * LD + fn]);
                bf[1] = __float_as_uint(Vc[(kt * 8 + lt + 4) * LD + fn]);
                mma_tf32(oacc[nt], af, bf);
            }
        }
    }

    // ---- epilogue: O/l + q residual (q gmem is k-interleaved; read via perm) ----
    {
        float li0 = 1.f / lrun0, li1 = 1.f / lrun1;
#pragma unroll
        for (int nt = 0; nt < 8; nt++) {
            int c = nt * 8 + lt * 2;                    // natural output col
            size_t a0 = (size_t)(b * S_ + i0 + r0) * HF_ + h * 64 + c;
            size_t a1 = (size_t)(b * S_ + i0 + r1) * HF_ + h * 64 + c;
            size_t qb0 = (size_t)(b * S_ + i0 + r0) * HF_ + h * 64 + nt * 8;
            size_t qb1 = (size_t)(b * S_ + i0 + r1) * HF_ + h * 64 + nt * 8;
            float q00 = q[qb0 + sp0], q01 = q[qb0 + sp1];
            float q10 = q[qb1 + sp0], q11 = q[qb1 + sp1];
            *(float2*)&enf[a0] = make_float2(oacc[nt][0] * li0 + q00, oacc[nt][1] * li0 + q01);
            *(float2*)&enf[a1] = make_float2(oacc[nt][2] * li1 + q10, oacc[nt][3] * li1 + q11);
        }
    }
}

// ---------------- per-(b,c) inv-std over S ----------------
__global__ __launch_bounds__(256) void gstats_kernel(
    const float* __restrict__ x, float* __restrict__ invv)
{
    const int c = blockIdx.x * 32 + threadIdx.x;
    const int b = blockIdx.y;
    const int ty = threadIdx.y;
    const float* xb = x + (size_t)b * S_ * HF_ + c;

    float sum = 0.f, ssq = 0.f;
    for (int s = ty; s < S_; s += 8) {
        float v = xb[(size_t)s * HF_];
        sum += v;
        ssq += v * v;
    }
    __shared__ float rs[8][32], rq[8][32];
    rs[ty][threadIdx.x] = sum;
    rq[ty][threadIdx.x] = ssq;
    __syncthreads();
    if (ty == 0) {
        float s = 0.f, qq = 0.f;
#pragma unroll
        for (int i = 0; i < 8; i++) { s += rs[i][threadIdx.x]; qq += rq[i][threadIdx.x]; }
        float mean = s * (1.f / (float)S_);
        float var = qq * (1.f / (float)S_) - mean * mean;
        invv[b * HF_ + c] = rsqrtf(var + EPS_);
    }
}

// ---------------- weff (elementwise) ----------------
__global__ __launch_bounds__(256) void weff_kernel(
    const float* __restrict__ W1, const float* __restrict__ invv,
    float* __restrict__ weff)
{
    const int b = blockIdx.y;
    const int c0 = blockIdx.x * 16;
    const int f = threadIdx.x & 63, cr = threadIdx.x >> 6;
#pragma unroll
    for (int i = 0; i < 4; i++) {
        int c = c0 + i * 4 + cr;
        float w = W1[c * F_ + f] + ((c & 63) == f ? 1.f : 0.f);
        weff[(size_t)b * HF_ * F_ + (size_t)c * F_ + f] = w * invv[b * HF_ + c];
    }
}

// ---------------- dense1 (legacy mma, 4-stage cp.async) ----------------
__global__ __launch_bounds__(256) void dense1_kernel(
    const float* __restrict__ X, const float* __restrict__ weff,
    float* __restrict__ out)
{
    __shared__ float dsm[4 * 2368];
    const int tid = threadIdx.x;
    const int lane = tid & 31, warp = tid >> 5;
    const int mw = warp & 3;
    const int wn = warp >> 2;
    const int m0 = blockIdx.x * 64;
    const int b = m0 >> 10;
    const float* Wb = weff + (size_t)b * HF_ * F_;

    float acc[4][4];
#pragma unroll
    for (int i = 0; i < 4; i++)
#pragma unroll
        for (int r = 0; r < 4; r++) acc[i][r] = 0.f;

    auto issue = [&](int k0, int stg) {
        float* As = dsm + stg * 2368;
        float* Ws = As + 1280;
        {
            int r = tid >> 2, c4 = tid & 3;
            cpasync16(&As[r * 20 + c4 * 4], &X[(size_t)(m0 + r) * HF_ + k0 + c4 * 4]);
        }
        {
            int r = tid >> 4, c4 = tid & 15;
            cpasync16(&Ws[r * 68 + c4 * 4], &Wb[(size_t)(k0 + r) * F_ + c4 * 4]);
        }
        cpasync_commit();
    };

    issue(0, 0);
    issue(16, 1);
    issue(32, 2);

    for (int it = 0; it < 64; it++) {
        cpasync_wait2();
        __syncthreads();
        if (it + 3 < 64) issue((it + 3) * 16, (it + 3) & 3);
        else cpasync_commit();

        const float* As = dsm + (it & 3) * 2368;
        const float* Ws = As + 1280;
#pragma unroll
        for (int kt = 0; kt < 2; kt++) {
            uint32_t af[4];
            const int rb = mw * 16 + (lane >> 2);
            const int ac = kt * 8 + (lane & 3);
            af[0] = __float_as_uint(As[rb * 20 + ac]);
            af[1] = __float_as_uint(As[(rb + 8) * 20 + ac]);
            af[2] = __float_as_uint(As[rb * 20 + ac + 4]);
            af[3] = __float_as_uint(As[(rb + 8) * 20 + ac + 4]);
            uint32_t bf[4][2];
#pragma unroll
            for (int nt = 0; nt < 4; nt++) {
                int bn = wn * 32 + nt * 8 + (lane >> 2);
                bf[nt][0] = __float_as_uint(Ws[(kt * 8 + (lane & 3)) * 68 + bn]);
                bf[nt][1] = __float_as_uint(Ws[(kt * 8 + (lane & 3) + 4) * 68 + bn]);
            }
#pragma unroll
            for (int nt = 0; nt < 4; nt++)
                mma_tf32(acc[nt], af, bf[nt]);
        }
    }
#pragma unroll
    for (int nt = 0; nt < 4; nt++) {
        int r = m0 + mw * 16 + (lane >> 2);
        int c = wn * 32 + nt * 8 + (lane & 3) * 2;
        out[(size_t)r * F_ + c]           = acc[nt][0];
        out[(size_t)r * F_ + c + 1]       = acc[nt][1];
        out[(size_t)(r + 8) * F_ + c]     = acc[nt][2];
        out[(size_t)(r + 8) * F_ + c + 1] = acc[nt][3];
    }
}

// ---------------- final per-channel instance norm (C=64) ----------------
__global__ __launch_bounds__(1024) void gnorm_final(
    const float* __restrict__ x, float* __restrict__ y)
{
    const int c = blockIdx.x * 32 + threadIdx.x;
    const int b = blockIdx.y;
    const int ty = threadIdx.y;
    const float* xb = x + (size_t)b * S_ * F_ + c;

    float sum = 0.f, ssq = 0.f;
    for (int s = ty; s < S_; s += 32) {
        float v = xb[(size_t)s * F_];
        sum += v;
        ssq += v * v;
    }
    __shared__ float rs[32][33], rq[32][33];
    __shared__ float smean[32], sinvs[32];
    rs[ty][threadIdx.x] = sum;
    rq[ty][threadIdx.x] = ssq;
    __syncthreads();
    if (ty == 0) {
        float s = 0.f, qq = 0.f;
#pragma unroll
        for (int i = 0; i < 32; i++) { s += rs[i][threadIdx.x]; qq += rq[i][threadIdx.x]; }
        float mean = s * (1.f / (float)S_);
        float var = qq * (1.f / (float)S_) - mean * mean;
        smean[threadIdx.x] = mean;
        sinvs[threadIdx.x] = rsqrtf(var + EPS_);
    }
    __syncthreads();
    const float mean = smean[threadIdx.x];
    const float inv = sinvs[threadIdx.x];
    float* yb = y + (size_t)b * S_ * F_ + c;
    for (int s = ty; s < S_; s += 32)
        yb[(size_t)s * F_] = (xb[(size_t)s * F_] - mean) * inv;
}

// ---------------- launch ----------------
extern "C" void kernel_launch(void* const* d_in, const int* in_sizes, int n_in,
                              void* d_out, int out_size)
{
    const float* qw = (const float*)d_in[0];
    const float* kw = (const float*)d_in[1];
    const float* vw = (const float*)d_in[2];
    const float* Wq = (const float*)d_in[3];
    const float* bq = (const float*)d_in[4];
    const float* Wk = (const float*)d_in[5];
    const float* bk = (const float*)d_in[6];
    const float* Wv = (const float*)d_in[7];
    const float* bv = (const float*)d_in[8];
    const float* W1 = (const float*)d_in[9];
    float* out = (float*)d_out;

    float *pq, *pk, *pv, *penf, *pout2, *pinv, *pweff;
    cudaGetSymbolAddress((void**)&pq,    g_q);
    cudaGetSymbolAddress((void**)&pk,    g_k);
    cudaGetSymbolAddress((void**)&pv,    g_v);
    cudaGetSymbolAddress((void**)&penf,  g_enf);
    cudaGetSymbolAddress((void**)&pout2, g_out2);
    cudaGetSymbolAddress((void**)&pinv,  g_inv);
    cudaGetSymbolAddress((void**)&pweff, g_weff);

    static bool attr_done = false;
    if (!attr_done) {
        cudaFuncSetAttribute(qkv_gemm,  cudaFuncAttributeMaxDynamicSharedMemorySize, 75776);
        cudaFuncSetAttribute(attn_tf32, cudaFuncAttributeMaxDynamicSharedMemorySize, 104448);
        attr_done = true;
    }

    qkv_gemm<<<dim3(8, 64, 3), 256, 75776>>>(qw, kw, vw, Wq, Wk, Wv, bq, bk, bv, pq, pk, pv);

    attn_tf32<<<dim3(S_ / 128, H_, B_), 256, 104448>>>(pq, pk, pv, penf);

    gstats_kernel<<<dim3(HF_ / 32, B_), dim3(32, 8)>>>(penf, pinv);
    weff_kernel<<<dim3(HF_ / 16, B_), 256>>>(W1, pinv, pweff);

    dense1_kernel<<<(B_ * S_) / 64, 256>>>(penf, pweff, pout2);

    gnorm_final<<<dim3(F_ / 32, B_), dim3(32, 32)>>>(pout2, out);
}

// round 11
// speedup vs baseline: 1.0788x; 1.0788x over previous
#include <cuda_runtime.h>
#include <cstdint>

#define B_  8
#define S_  1024
#define D_  1024
#define H_  16
#define F_  64
#define HF_ 1024
#define EPS_ 1e-3f

// ---------------- scratch ----------------
__device__ float g_q[B_ * S_ * HF_];
__device__ float g_k[B_ * S_ * HF_];
__device__ float g_v[B_ * S_ * HF_];
__device__ float g_enf[B_ * S_ * HF_];
__device__ float g_out2[B_ * S_ * F_];
__device__ float g_psum[8 * B_ * HF_];
__device__ float g_pssq[8 * B_ * HF_];
__device__ float g_weff[B_ * HF_ * F_];

// ---------------- tf32 mma.m16n8k8 ----------------
__device__ __forceinline__ void mma_tf32(float* d, const uint32_t* a, const uint32_t* b) {
    asm volatile(
        "mma.sync.aligned.m16n8k8.row.col.f32.tf32.tf32.f32 "
        "{%0,%1,%2,%3}, {%4,%5,%6,%7}, {%8,%9}, {%0,%1,%2,%3};\n"
        : "+f"(d[0]), "+f"(d[1]), "+f"(d[2]), "+f"(d[3])
        : "r"(a[0]), "r"(a[1]), "r"(a[2]), "r"(a[3]), "r"(b[0]), "r"(b[1]));
}

// ---------------- cp.async helpers ----------------
__device__ __forceinline__ void cpasync16(void* smem, const void* g) {
    uint32_t s = (uint32_t)__cvta_generic_to_shared(smem);
    asm volatile("cp.async.cg.shared.global [%0], [%1], 16;\n" :: "r"(s), "l"(g));
}
__device__ __forceinline__ void cpasync_commit() {
    asm volatile("cp.async.commit_group;\n" ::: "memory");
}
__device__ __forceinline__ void cpasync_wait0() {
    asm volatile("cp.async.wait_group 0;\n" ::: "memory");
}
__device__ __forceinline__ void cpasync_wait2() {
    asm volatile("cp.async.wait_group 2;\n" ::: "memory");
}

// ---------------- fast exp (FMA pipe) ----------------
__device__ __forceinline__ float fexp(float x) {
    float t = fmaxf(x * 1.4426950408889634f, -126.0f);
    int   i = __float2int_rn(t);
    float f = t - (float)i;
    float p = 0.0013333558146428443f;
    p = fmaf(p, f, 0.009618129842126066f);
    p = fmaf(p, f, 0.05550410866482158f);
    p = fmaf(p, f, 0.2402265069591007f);
    p = fmaf(p, f, 0.6931471805599453f);
    p = fmaf(p, f, 1.0f);
    return p * __int_as_float((i + 127) << 23);
}

// ---------------- merged QKV GEMM, 4-stage cp.async ring (R8 exact) ----------------
__global__ __launch_bounds__(256) void qkv_gemm(
    const float* __restrict__ A0, const float* __restrict__ A1, const float* __restrict__ A2,
    const float* __restrict__ W0, const float* __restrict__ W1p, const float* __restrict__ W2,
    const float* __restrict__ b0, const float* __restrict__ b1p, const float* __restrict__ b2,
    float* __restrict__ C0, float* __restrict__ C1, float* __restrict__ C2)
{
    extern __shared__ float gsm[];
    const int z = blockIdx.z;
    const float* A    = z == 0 ? A0 : (z == 1 ? A1 : A2);
    const float* W    = z == 0 ? W0 : (z == 1 ? W1p : W2);
    const float* bias = z == 0 ? b0 : (z == 1 ? b1p : b2);
    float*       C    = z == 0 ? C0 : (z == 1 ? C1 : C2);

    const int tid  = threadIdx.x;
    const int lane = tid & 31, warp = tid >> 5;
    const int wm   = warp & 1, wn = warp >> 1;
    const int m0   = blockIdx.y * 128;
    const int n0   = blockIdx.x * 128;

    float acc[4][4][4];
#pragma unroll
    for (int i = 0; i < 4; i++)
#pragma unroll
        for (int j = 0; j < 4; j++)
#pragma unroll
            for (int r = 0; r < 4; r++) acc[i][j][r] = 0.f;

    auto issue = [&](int k0, int stg) {
        float* As = gsm + stg * 4736;
        float* Ws = As + 2560;
#pragma unroll
        for (int t = 0; t < 2; t++) {
            int idx = tid + t * 256;
            int r = idx >> 2, c4 = idx & 3;
            cpasync16(&As[r * 20 + c4 * 4], &A[(size_t)(m0 + r) * D_ + k0 + c4 * 4]);
        }
#pragma unroll
        for (int t = 0; t < 2; t++) {
            int idx = tid + t * 256;
            int r = idx >> 5, c8 = idx & 31;
            cpasync16(&Ws[r * 136 + c8 * 4], &W[(size_t)(k0 + r) * HF_ + n0 + c8 * 4]);
        }
        cpasync_commit();
    };

    issue(0, 0);
    issue(16, 1);
    issue(32, 2);

    for (int it = 0; it < 64; it++) {
        cpasync_wait2();
        __syncthreads();
        if (it + 3 < 64) issue((it + 3) * 16, (it + 3) & 3);
        else cpasync_commit();

        const float* As = gsm + (it & 3) * 4736;
        const float* Ws = As + 2560;
#pragma unroll
        for (int kt = 0; kt < 2; kt++) {
            uint32_t af[4][4];
            const int ar = lane >> 2, ac = kt * 8 + (lane & 3);
#pragma unroll
            for (int mt = 0; mt < 4; mt++) {
                int rb = wm * 64 + mt * 16 + ar;
                af[mt][0] = __float_as_uint(As[rb * 20 + ac]);
                af[mt][1] = __float_as_uint(As[(rb + 8) * 20 + ac]);
                af[mt][2] = __float_as_uint(As[rb * 20 + ac + 4]);
                af[mt][3] = __float_as_uint(As[(rb + 8) * 20 + ac + 4]);
            }
            uint32_t bf[4][2];
#pragma unroll
            for (int nt = 0; nt < 4; nt++) {
                int bn = wn * 32 + nt * 8 + (lane >> 2);
                bf[nt][0] = __float_as_uint(Ws[(kt * 8 + (lane & 3)) * 136 + bn]);
                bf[nt][1] = __float_as_uint(Ws[(kt * 8 + (lane & 3) + 4) * 136 + bn]);
            }
#pragma unroll
            for (int mt = 0; mt < 4; mt++)
#pragma unroll
                for (int nt = 0; nt < 4; nt++)
                    mma_tf32(acc[mt][nt], af[mt], bf[nt]);
        }
    }

#pragma unroll
    for (int mt = 0; mt < 4; mt++) {
#pragma unroll
        for (int nt = 0; nt < 4; nt++) {
            int r = m0 + wm * 64 + mt * 16 + (lane >> 2);
            int c = n0 + wn * 32 + nt * 8 + (lane & 3) * 2;
            float bv0 = bias[c], bv1 = bias[c + 1];
            *(float2*)&C[(size_t)r * HF_ + c] =
                make_float2(acc[mt][nt][0] + bv0, acc[mt][nt][1] + bv1);
            *(float2*)&C[(size_t)(r + 8) * HF_ + c] =
                make_float2(acc[mt][nt][2] + bv0, acc[mt][nt][3] + bv1);
        }
    }
}

// ---------------- flash attention: 128-q tile, maxless softmax (R8 exact) ----------------
#define LD 68
__global__ __launch_bounds__(256, 2) void attn_tf32(
    const float* __restrict__ q, const float* __restrict__ k,
    const float* __restrict__ v, float* __restrict__ enf)
{
    extern __shared__ float sm[];
    float* Ks = sm;                    // [2][64*LD]
    float* Vs = Ks + 2 * 64 * LD;      // [2][64*LD]
    float* Ps = Vs + 2 * 64 * LD;      // [128*LD]

    const int b = blockIdx.z, h = blockIdx.y, i0 = blockIdx.x * 128;
    const int tid = threadIdx.x, lane = tid & 31, warp = tid >> 5;
    const int r0 = warp * 16 + (lane >> 2), r1 = r0 + 8;
    const int lt = lane & 3;

    auto issue = [&](int c0, int stg) {
        const float* kb = k + (size_t)(b * S_ + c0) * HF_ + h * 64;
        const float* vb = v + (size_t)(b * S_ + c0) * HF_ + h * 64;
        float* Kd = Ks + stg * 64 * LD;
        float* Vd = Vs + stg * 64 * LD;
#pragma unroll
        for (int t = 0; t < 4; t++) {
            int idx = tid + t * 256;
            int r = idx >> 4, c4 = idx & 15;
            cpasync16(&Kd[r * LD + c4 * 4], kb + (size_t)r * HF_ + c4 * 4);
            cpasync16(&Vd[r * LD + c4 * 4], vb + (size_t)r * HF_ + c4 * 4);
        }
        cpasync_commit();
    };

    issue(0, 0);

    for (int idx = tid; idx < 128 * 16; idx += 256) {
        int r = idx >> 4, c4 = idx & 15;
        float4 vq = *(const float4*)&q[(size_t)(b * S_ + i0 + r) * HF_ + h * 64 + c4 * 4];
        vq.x *= 0.125f; vq.y *= 0.125f; vq.z *= 0.125f; vq.w *= 0.125f;
        *(float4*)&Ps[r * LD + c4 * 4] = vq;
    }
    __syncthreads();

    uint32_t qf[8][4];
#pragma unroll
    for (int kt = 0; kt < 8; kt++) {
        const int ac = kt * 8 + lt;
        qf[kt][0] = __float_as_uint(Ps[r0 * LD + ac]);
        qf[kt][1] = __float_as_uint(Ps[r1 * LD + ac]);
        qf[kt][2] = __float_as_uint(Ps[r0 * LD + ac + 4]);
        qf[kt][3] = __float_as_uint(Ps[r1 * LD + ac + 4]);
    }

    float lrun0 = 0.f, lrun1 = 0.f;
    float oacc[8][4];
#pragma unroll
    for (int i = 0; i < 8; i++)
#pragma unroll
        for (int j = 0; j < 4; j++) oacc[i][j] = 0.f;

    for (int it = 0; it < 16; it++) {
        cpasync_wait0();
        __syncthreads();
        if (it < 15) issue((it + 1) * 64, (it + 1) & 1);

        const float* Kc = Ks + (it & 1) * 64 * LD;
        const float* Vc = Vs + (it & 1) * 64 * LD;

        float sacc[8][4];
#pragma unroll
        for (int i = 0; i < 8; i++)
#pragma unroll
            for (int j = 0; j < 4; j++) sacc[i][j] = 0.f;
#pragma unroll
        for (int kt = 0; kt < 8; kt++) {
#pragma unroll
            for (int nt = 0; nt < 8; nt++) {
                uint32_t bf[2];
                int jn = nt * 8 + (lane >> 2);
                bf[0] = __float_as_uint(Kc[jn * LD + kt * 8 + lt]);
                bf[1] = __float_as_uint(Kc[jn * LD + kt * 8 + lt + 4]);
                mma_tf32(sacc[nt], qf[kt], bf);
            }
        }

        float sum0 = 0.f, sum1 = 0.f;
#pragma unroll
        for (int nt = 0; nt < 8; nt++) {
            float e0 = fexp(sacc[nt][0]);
            float e1 = fexp(sacc[nt][1]);
            float e2 = fexp(sacc[nt][2]);
            float e3 = fexp(sacc[nt][3]);
            sum0 += e0 + e1; sum1 += e2 + e3;
            int c = nt * 8 + lt * 2;
            *(float2*)&Ps[r0 * LD + c] = make_float2(e0, e1);
            *(float2*)&Ps[r1 * LD + c] = make_float2(e2, e3);
        }
        sum0 += __shfl_xor_sync(0xffffffffu, sum0, 1);
        sum0 += __shfl_xor_sync(0xffffffffu, sum0, 2);
        sum1 += __shfl_xor_sync(0xffffffffu, sum1, 1);
        sum1 += __shfl_xor_sync(0xffffffffu, sum1, 2);
        lrun0 += sum0;
        lrun1 += sum1;
        __syncwarp();

#pragma unroll
        for (int kt = 0; kt < 8; kt++) {
            uint32_t af[4];
            const int ac = kt * 8 + lt;
            af[0] = __float_as_uint(Ps[r0 * LD + ac]);
            af[1] = __float_as_uint(Ps[r1 * LD + ac]);
            af[2] = __float_as_uint(Ps[r0 * LD + ac + 4]);
            af[3] = __float_as_uint(Ps[r1 * LD + ac + 4]);
#pragma unroll
            for (int nt = 0; nt < 8; nt++) {
                uint32_t bf[2];
                int fn = nt * 8 + (lane >> 2);
                bf[0] = __float_as_uint(Vc[(kt * 8 + lt) * LD + fn]);
                bf[1] = __float_as_uint(Vc[(kt * 8 + lt + 4) * LD + fn]);
                mma_tf32(oacc[nt], af, bf);
            }
        }
    }

    {
        float li0 = 1.f / lrun0, li1 = 1.f / lrun1;
#pragma unroll
        for (int nt = 0; nt < 8; nt++) {
            int c = nt * 8 + lt * 2;
            size_t a0 = (size_t)(b * S_ + i0 + r0) * HF_ + h * 64 + c;
            size_t a1 = (size_t)(b * S_ + i0 + r1) * HF_ + h * 64 + c;
            float2 q0 = *(const float2*)&q[a0];
            float2 q1 = *(const float2*)&q[a1];
            *(float2*)&enf[a0] = make_float2(oacc[nt][0] * li0 + q0.x, oacc[nt][1] * li0 + q0.y);
            *(float2*)&enf[a1] = make_float2(oacc[nt][2] * li1 + q1.x, oacc[nt][3] * li1 + q1.y);
        }
    }
}

// ---------------- stage A: per-(b,c) partial sums over 128-row slabs ----------------
// grid (HF/32, B, 8); deterministic (no atomics).
__global__ __launch_bounds__(256) void gstats_part(
    const float* __restrict__ x, float* __restrict__ psum, float* __restrict__ pssq)
{
    const int c = blockIdx.x * 32 + threadIdx.x;
    const int b = blockIdx.y;
    const int zz = blockIdx.z;
    const int ty = threadIdx.y;
    const float* xb = x + ((size_t)b * S_ + zz * 128) * HF_ + c;

    float sum = 0.f, ssq = 0.f;
#pragma unroll 4
    for (int s = ty; s < 128; s += 8) {
        float v = xb[(size_t)s * HF_];
        sum += v;
        ssq += v * v;
    }
    __shared__ float rs[8][32], rq[8][32];
    rs[ty][threadIdx.x] = sum;
    rq[ty][threadIdx.x] = ssq;
    __syncthreads();
    if (ty == 0) {
        float s = 0.f, qq = 0.f;
#pragma unroll
        for (int i = 0; i < 8; i++) { s += rs[i][threadIdx.x]; qq += rq[i][threadIdx.x]; }
        psum[(size_t)(zz * B_ + b) * HF_ + c] = s;
        pssq[(size_t)(zz * B_ + b) * HF_ + c] = qq;
    }
}

// ---------------- weff: fold partials -> inv, elementwise weight scale ----------------
__global__ __launch_bounds__(256) void weff_kernel(
    const float* __restrict__ W1,
    const float* __restrict__ psum, const float* __restrict__ pssq,
    float* __restrict__ weff)
{
    const int b = blockIdx.y;
    const int c0 = blockIdx.x * 16;
    const int f = threadIdx.x & 63, cr = threadIdx.x >> 6;
#pragma unroll
    for (int i = 0; i < 4; i++) {
        int c = c0 + i * 4 + cr;
        float s = 0.f, qq = 0.f;
#pragma unroll
        for (int zz = 0; zz < 8; zz++) {
            s  += psum[(size_t)(zz * B_ + b) * HF_ + c];
            qq += pssq[(size_t)(zz * B_ + b) * HF_ + c];
        }
        float mean = s * (1.f / (float)S_);
        float var = qq * (1.f / (float)S_) - mean * mean;
        float iv = rsqrtf(var + EPS_);
        float w = W1[c * F_ + f] + ((c & 63) == f ? 1.f : 0.f);
        weff[(size_t)b * HF_ * F_ + (size_t)c * F_ + f] = w * iv;
    }
}

// ---------------- dense1 (legacy mma, 4-stage cp.async) ----------------
__global__ __launch_bounds__(256) void dense1_kernel(
    const float* __restrict__ X, const float* __restrict__ weff,
    float* __restrict__ out)
{
    __shared__ float dsm[4 * 2368];
    const int tid = threadIdx.x;
    const int lane = tid & 31, warp = tid >> 5;
    const int mw = warp & 3;
    const int wn = warp >> 2;
    const int m0 = blockIdx.x * 64;
    const int b = m0 >> 10;
    const float* Wb = weff + (size_t)b * HF_ * F_;

    float acc[4][4];
#pragma unroll
    for (int i = 0; i < 4; i++)
#pragma unroll
        for (int r = 0; r < 4; r++) acc[i][r] = 0.f;

    auto issue = [&](int k0, int stg) {
        float* As = dsm + stg * 2368;
        float* Ws = As + 1280;
        {
            int r = tid >> 2, c4 = tid & 3;
            cpasync16(&As[r * 20 + c4 * 4], &X[(size_t)(m0 + r) * HF_ + k0 + c4 * 4]);
        }
        {
            int r = tid >> 4, c4 = tid & 15;
            cpasync16(&Ws[r * 68 + c4 * 4], &Wb[(size_t)(k0 + r) * F_ + c4 * 4]);
        }
        cpasync_commit();
    };

    issue(0, 0);
    issue(16, 1);
    issue(32, 2);

    for (int it = 0; it < 64; it++) {
        cpasync_wait2();
        __syncthreads();
        if (it + 3 < 64) issue((it + 3) * 16, (it + 3) & 3);
        else cpasync_commit();

        const float* As = dsm + (it & 3) * 2368;
        const float* Ws = As + 1280;
#pragma unroll
        for (int kt = 0; kt < 2; kt++) {
            uint32_t af[4];
            const int rb = mw * 16 + (lane >> 2);
            const int ac = kt * 8 + (lane & 3);
            af[0] = __float_as_uint(As[rb * 20 + ac]);
            af[1] = __float_as_uint(As[(rb + 8) * 20 + ac]);
            af[2] = __float_as_uint(As[rb * 20 + ac + 4]);
            af[3] = __float_as_uint(As[(rb + 8) * 20 + ac + 4]);
            uint32_t bf[4][2];
#pragma unroll
            for (int nt = 0; nt < 4; nt++) {
                int bn = wn * 32 + nt * 8 + (lane >> 2);
                bf[nt][0] = __float_as_uint(Ws[(kt * 8 + (lane & 3)) * 68 + bn]);
                bf[nt][1] = __float_as_uint(Ws[(kt * 8 + (lane & 3) + 4) * 68 + bn]);
            }
#pragma unroll
            for (int nt = 0; nt < 4; nt++)
                mma_tf32(acc[nt], af, bf[nt]);
        }
    }
#pragma unroll
    for (int nt = 0; nt < 4; nt++) {
        int r = m0 + mw * 16 + (lane >> 2);
        int c = wn * 32 + nt * 8 + (lane & 3) * 2;
        out[(size_t)r * F_ + c]           = acc[nt][0];
        out[(size_t)r * F_ + c + 1]       = acc[nt][1];
        out[(size_t)(r + 8) * F_ + c]     = acc[nt][2];
        out[(size_t)(r + 8) * F_ + c + 1] = acc[nt][3];
    }
}

// ---------------- final per-channel instance norm (C=64) ----------------
__global__ __launch_bounds__(1024) void gnorm_final(
    const float* __restrict__ x, float* __restrict__ y)
{
    const int c = blockIdx.x * 32 + threadIdx.x;
    const int b = blockIdx.y;
    const int ty = threadIdx.y;
    const float* xb = x + (size_t)b * S_ * F_ + c;

    float sum = 0.f, ssq = 0.f;
    for (int s = ty; s < S_; s += 32) {
        float v = xb[(size_t)s * F_];
        sum += v;
        ssq += v * v;
    }
    __shared__ float rs[32][33], rq[32][33];
    __shared__ float smean[32], sinvs[32];
    rs[ty][threadIdx.x] = sum;
    rq[ty][threadIdx.x] = ssq;
    __syncthreads();
    if (ty == 0) {
        float s = 0.f, qq = 0.f;
#pragma unroll
        for (int i = 0; i < 32; i++) { s += rs[i][threadIdx.x]; qq += rq[i][threadIdx.x]; }
        float mean = s * (1.f / (float)S_);
        float var = qq * (1.f / (float)S_) - mean * mean;
        smean[threadIdx.x] = mean;
        sinvs[threadIdx.x] = rsqrtf(var + EPS_);
    }
    __syncthreads();
    const float mean = smean[threadIdx.x];
    const float inv = sinvs[threadIdx.x];
    float* yb = y + (size_t)b * S_ * F_ + c;
    for (int s = ty; s < S_; s += 32)
        yb[(size_t)s * F_] = (xb[(size_t)s * F_] - mean) * inv;
}

// ---------------- launch ----------------
extern "C" void kernel_launch(void* const* d_in, const int* in_sizes, int n_in,
                              void* d_out, int out_size)
{
    const float* qw = (const float*)d_in[0];
    const float* kw = (const float*)d_in[1];
    const float* vw = (const float*)d_in[2];
    const float* Wq = (const float*)d_in[3];
    const float* bq = (const float*)d_in[4];
    const float* Wk = (const float*)d_in[5];
    const float* bk = (const float*)d_in[6];
    const float* Wv = (const float*)d_in[7];
    const float* bv = (const float*)d_in[8];
    const float* W1 = (const float*)d_in[9];
    float* out = (float*)d_out;

    float *pq, *pk, *pv, *penf, *pout2, *ppsum, *ppssq, *pweff;
    cudaGetSymbolAddress((void**)&pq,    g_q);
    cudaGetSymbolAddress((void**)&pk,    g_k);
    cudaGetSymbolAddress((void**)&pv,    g_v);
    cudaGetSymbolAddress((void**)&penf,  g_enf);
    cudaGetSymbolAddress((void**)&pout2, g_out2);
    cudaGetSymbolAddress((void**)&ppsum, g_psum);
    cudaGetSymbolAddress((void**)&ppssq, g_pssq);
    cudaGetSymbolAddress((void**)&pweff, g_weff);

    static bool attr_done = false;
    if (!attr_done) {
        cudaFuncSetAttribute(qkv_gemm,  cudaFuncAttributeMaxDynamicSharedMemorySize, 75776);
        cudaFuncSetAttribute(attn_tf32, cudaFuncAttributeMaxDynamicSharedMemorySize, 104448);
        attr_done = true;
    }

    qkv_gemm<<<dim3(8, 64, 3), 256, 75776>>>(qw, kw, vw, Wq, Wk, Wv, bq, bk, bv, pq, pk, pv);

    attn_tf32<<<dim3(S_ / 128, H_, B_), 256, 104448>>>(pq, pk, pv, penf);

    gstats_part<<<dim3(HF_ / 32, B_, 8), dim3(32, 8)>>>(penf, ppsum, ppssq);
    weff_kernel<<<dim3(HF_ / 16, B_), 256>>>(W1, ppsum, ppssq, pweff);

    dense1_kernel<<<(B_ * S_) / 64, 256>>>(penf, pweff, pout2);

    gnorm_final<<<dim3(F_ / 32, B_), dim3(32, 32)>>>(pout2, out);
}

// round 12
// speedup vs baseline: 1.0908x; 1.0111x over previous
#include <cuda_runtime.h>
#include <cstdint>

#define B_  8
#define S_  1024
#define D_  1024
#define H_  16
#define F_  64
#define HF_ 1024
#define EPS_ 1e-3f

// ---------------- scratch ----------------
__device__ float g_q[B_ * S_ * HF_];
__device__ float g_k[B_ * S_ * HF_];
__device__ float g_v[B_ * S_ * HF_];
__device__ float g_enf[B_ * S_ * HF_];
__device__ float g_out2[2 * B_ * S_ * F_];   // two split-K partials
__device__ float g_psum[8 * B_ * HF_];
__device__ float g_pssq[8 * B_ * HF_];
__device__ float g_weff[B_ * HF_ * F_];

// ---------------- tf32 mma.m16n8k8 ----------------
__device__ __forceinline__ void mma_tf32(float* d, const uint32_t* a, const uint32_t* b) {
    asm volatile(
        "mma.sync.aligned.m16n8k8.row.col.f32.tf32.tf32.f32 "
        "{%0,%1,%2,%3}, {%4,%5,%6,%7}, {%8,%9}, {%0,%1,%2,%3};\n"
        : "+f"(d[0]), "+f"(d[1]), "+f"(d[2]), "+f"(d[3])
        : "r"(a[0]), "r"(a[1]), "r"(a[2]), "r"(a[3]), "r"(b[0]), "r"(b[1]));
}

// ---------------- cp.async helpers ----------------
__device__ __forceinline__ void cpasync16(void* smem, const void* g) {
    uint32_t s = (uint32_t)__cvta_generic_to_shared(smem);
    asm volatile("cp.async.cg.shared.global [%0], [%1], 16;\n" :: "r"(s), "l"(g));
}
__device__ __forceinline__ void cpasync_commit() {
    asm volatile("cp.async.commit_group;\n" ::: "memory");
}
__device__ __forceinline__ void cpasync_wait0() {
    asm volatile("cp.async.wait_group 0;\n" ::: "memory");
}
__device__ __forceinline__ void cpasync_wait2() {
    asm volatile("cp.async.wait_group 2;\n" ::: "memory");
}

// ---------------- fast exp (FMA pipe) ----------------
__device__ __forceinline__ float fexp(float x) {
    float t = fmaxf(x * 1.4426950408889634f, -126.0f);
    int   i = __float2int_rn(t);
    float f = t - (float)i;
    float p = 0.0013333558146428443f;
    p = fmaf(p, f, 0.009618129842126066f);
    p = fmaf(p, f, 0.05550410866482158f);
    p = fmaf(p, f, 0.2402265069591007f);
    p = fmaf(p, f, 0.6931471805599453f);
    p = fmaf(p, f, 1.0f);
    return p * __int_as_float((i + 127) << 23);
}

// ---------------- merged QKV GEMM, 4-stage cp.async ring (unchanged) ----------------
__global__ __launch_bounds__(256) void qkv_gemm(
    const float* __restrict__ A0, const float* __restrict__ A1, const float* __restrict__ A2,
    const float* __restrict__ W0, const float* __restrict__ W1p, const float* __restrict__ W2,
    const float* __restrict__ b0, const float* __restrict__ b1p, const float* __restrict__ b2,
    float* __restrict__ C0, float* __restrict__ C1, float* __restrict__ C2)
{
    extern __shared__ float gsm[];
    const int z = blockIdx.z;
    const float* A    = z == 0 ? A0 : (z == 1 ? A1 : A2);
    const float* W    = z == 0 ? W0 : (z == 1 ? W1p : W2);
    const float* bias = z == 0 ? b0 : (z == 1 ? b1p : b2);
    float*       C    = z == 0 ? C0 : (z == 1 ? C1 : C2);

    const int tid  = threadIdx.x;
    const int lane = tid & 31, warp = tid >> 5;
    const int wm   = warp & 1, wn = warp >> 1;
    const int m0   = blockIdx.y * 128;
    const int n0   = blockIdx.x * 128;

    float acc[4][4][4];
#pragma unroll
    for (int i = 0; i < 4; i++)
#pragma unroll
        for (int j = 0; j < 4; j++)
#pragma unroll
            for (int r = 0; r < 4; r++) acc[i][j][r] = 0.f;

    auto issue = [&](int k0, int stg) {
        float* As = gsm + stg * 4736;
        float* Ws = As + 2560;
#pragma unroll
        for (int t = 0; t < 2; t++) {
            int idx = tid + t * 256;
            int r = idx >> 2, c4 = idx & 3;
            cpasync16(&As[r * 20 + c4 * 4], &A[(size_t)(m0 + r) * D_ + k0 + c4 * 4]);
        }
#pragma unroll
        for (int t = 0; t < 2; t++) {
            int idx = tid + t * 256;
            int r = idx >> 5, c8 = idx & 31;
            cpasync16(&Ws[r * 136 + c8 * 4], &W[(size_t)(k0 + r) * HF_ + n0 + c8 * 4]);
        }
        cpasync_commit();
    };

    issue(0, 0);
    issue(16, 1);
    issue(32, 2);

    for (int it = 0; it < 64; it++) {
        cpasync_wait2();
        __syncthreads();
        if (it + 3 < 64) issue((it + 3) * 16, (it + 3) & 3);
        else cpasync_commit();

        const float* As = gsm + (it & 3) * 4736;
        const float* Ws = As + 2560;
#pragma unroll
        for (int kt = 0; kt < 2; kt++) {
            uint32_t af[4][4];
            const int ar = lane >> 2, ac = kt * 8 + (lane & 3);
#pragma unroll
            for (int mt = 0; mt < 4; mt++) {
                int rb = wm * 64 + mt * 16 + ar;
                af[mt][0] = __float_as_uint(As[rb * 20 + ac]);
                af[mt][1] = __float_as_uint(As[(rb + 8) * 20 + ac]);
                af[mt][2] = __float_as_uint(As[rb * 20 + ac + 4]);
                af[mt][3] = __float_as_uint(As[(rb + 8) * 20 + ac + 4]);
            }
            uint32_t bf[4][2];
#pragma unroll
            for (int nt = 0; nt < 4; nt++) {
                int bn = wn * 32 + nt * 8 + (lane >> 2);
                bf[nt][0] = __float_as_uint(Ws[(kt * 8 + (lane & 3)) * 136 + bn]);
                bf[nt][1] = __float_as_uint(Ws[(kt * 8 + (lane & 3) + 4) * 136 + bn]);
            }
#pragma unroll
            for (int mt = 0; mt < 4; mt++)
#pragma unroll
                for (int nt = 0; nt < 4; nt++)
                    mma_tf32(acc[mt][nt], af[mt], bf[nt]);
        }
    }

#pragma unroll
    for (int mt = 0; mt < 4; mt++) {
#pragma unroll
        for (int nt = 0; nt < 4; nt++) {
            int r = m0 + wm * 64 + mt * 16 + (lane >> 2);
            int c = n0 + wn * 32 + nt * 8 + (lane & 3) * 2;
            float bv0 = bias[c], bv1 = bias[c + 1];
            *(float2*)&C[(size_t)r * HF_ + c] =
                make_float2(acc[mt][nt][0] + bv0, acc[mt][nt][1] + bv1);
            *(float2*)&C[(size_t)(r + 8) * HF_ + c] =
                make_float2(acc[mt][nt][2] + bv0, acc[mt][nt][3] + bv1);
        }
    }
}

// ---------------- flash attention + fused per-slab stats ----------------
#define LD 68
__global__ __launch_bounds__(256, 2) void attn_tf32(
    const float* __restrict__ q, const float* __restrict__ k,
    const float* __restrict__ v, float* __restrict__ enf,
    float* __restrict__ psum, float* __restrict__ pssq)
{
    extern __shared__ float sm[];
    float* Ks = sm;                    // [2][64*LD]
    float* Vs = Ks + 2 * 64 * LD;      // [2][64*LD]
    float* Ps = Vs + 2 * 64 * LD;      // [128*LD]

    const int b = blockIdx.z, h = blockIdx.y, i0 = blockIdx.x * 128;
    const int tid = threadIdx.x, lane = tid & 31, warp = tid >> 5;
    const int r0 = warp * 16 + (lane >> 2), r1 = r0 + 8;
    const int lt = lane & 3;

    auto issue = [&](int c0, int stg) {
        const float* kb = k + (size_t)(b * S_ + c0) * HF_ + h * 64;
        const float* vb = v + (size_t)(b * S_ + c0) * HF_ + h * 64;
        float* Kd = Ks + stg * 64 * LD;
        float* Vd = Vs + stg * 64 * LD;
#pragma unroll
        for (int t = 0; t < 4; t++) {
            int idx = tid + t * 256;
            int r = idx >> 4, c4 = idx & 15;
            cpasync16(&Kd[r * LD + c4 * 4], kb + (size_t)r * HF_ + c4 * 4);
            cpasync16(&Vd[r * LD + c4 * 4], vb + (size_t)r * HF_ + c4 * 4);
        }
        cpasync_commit();
    };

    issue(0, 0);

    for (int idx = tid; idx < 128 * 16; idx += 256) {
        int r = idx >> 4, c4 = idx & 15;
        float4 vq = *(const float4*)&q[(size_t)(b * S_ + i0 + r) * HF_ + h * 64 + c4 * 4];
        vq.x *= 0.125f; vq.y *= 0.125f; vq.z *= 0.125f; vq.w *= 0.125f;
        *(float4*)&Ps[r * LD + c4 * 4] = vq;
    }
    __syncthreads();

    uint32_t qf[8][4];
#pragma unroll
    for (int kt = 0; kt < 8; kt++) {
        const int ac = kt * 8 + lt;
        qf[kt][0] = __float_as_uint(Ps[r0 * LD + ac]);
        qf[kt][1] = __float_as_uint(Ps[r1 * LD + ac]);
        qf[kt][2] = __float_as_uint(Ps[r0 * LD + ac + 4]);
        qf[kt][3] = __float_as_uint(Ps[r1 * LD + ac + 4]);
    }

    float lrun0 = 0.f, lrun1 = 0.f;
    float oacc[8][4];
#pragma unroll
    for (int i = 0; i < 8; i++)
#pragma unroll
        for (int j = 0; j < 4; j++) oacc[i][j] = 0.f;

    for (int it = 0; it < 16; it++) {
        cpasync_wait0();
        __syncthreads();
        if (it < 15) issue((it + 1) * 64, (it + 1) & 1);

        const float* Kc = Ks + (it & 1) * 64 * LD;
        const float* Vc = Vs + (it & 1) * 64 * LD;

        float sacc[8][4];
#pragma unroll
        for (int i = 0; i < 8; i++)
#pragma unroll
            for (int j = 0; j < 4; j++) sacc[i][j] = 0.f;
#pragma unroll
        for (int kt = 0; kt < 8; kt++) {
#pragma unroll
            for (int nt = 0; nt < 8; nt++) {
                uint32_t bf[2];
                int jn = nt * 8 + (lane >> 2);
                bf[0] = __float_as_uint(Kc[jn * LD + kt * 8 + lt]);
                bf[1] = __float_as_uint(Kc[jn * LD + kt * 8 + lt + 4]);
                mma_tf32(sacc[nt], qf[kt], bf);
            }
        }

        float sum0 = 0.f, sum1 = 0.f;
#pragma unroll
        for (int nt = 0; nt < 8; nt++) {
            float e0 = fexp(sacc[nt][0]);
            float e1 = fexp(sacc[nt][1]);
            float e2 = fexp(sacc[nt][2]);
            float e3 = fexp(sacc[nt][3]);
            sum0 += e0 + e1; sum1 += e2 + e3;
            int c = nt * 8 + lt * 2;
            *(float2*)&Ps[r0 * LD + c] = make_float2(e0, e1);
            *(float2*)&Ps[r1 * LD + c] = make_float2(e2, e3);
        }
        sum0 += __shfl_xor_sync(0xffffffffu, sum0, 1);
        sum0 += __shfl_xor_sync(0xffffffffu, sum0, 2);
        sum1 += __shfl_xor_sync(0xffffffffu, sum1, 1);
        sum1 += __shfl_xor_sync(0xffffffffu, sum1, 2);
        lrun0 += sum0;
        lrun1 += sum1;
        __syncwarp();

#pragma unroll
        for (int kt = 0; kt < 8; kt++) {
            uint32_t af[4];
            const int ac = kt * 8 + lt;
            af[0] = __float_as_uint(Ps[r0 * LD + ac]);
            af[1] = __float_as_uint(Ps[r1 * LD + ac]);
            af[2] = __float_as_uint(Ps[r0 * LD + ac + 4]);
            af[3] = __float_as_uint(Ps[r1 * LD + ac + 4]);
#pragma unroll
            for (int nt = 0; nt < 8; nt++) {
                uint32_t bf[2];
                int fn = nt * 8 + (lane >> 2);
                bf[0] = __float_as_uint(Vc[(kt * 8 + lt) * LD + fn]);
                bf[1] = __float_as_uint(Vc[(kt * 8 + lt + 4) * LD + fn]);
                mma_tf32(oacc[nt], af, bf);
            }
        }
    }

    // ---- epilogue: O/l + q residual, with fused per-channel partial stats ----
    float cs[8][2], cq[8][2];
    {
        float li0 = 1.f / lrun0, li1 = 1.f / lrun1;
#pragma unroll
        for (int nt = 0; nt < 8; nt++) {
            int c = nt * 8 + lt * 2;
            size_t a0 = (size_t)(b * S_ + i0 + r0) * HF_ + h * 64 + c;
            size_t a1 = (size_t)(b * S_ + i0 + r1) * HF_ + h * 64 + c;
            float2 q0 = *(const float2*)&q[a0];
            float2 q1 = *(const float2*)&q[a1];
            float2 o0 = make_float2(oacc[nt][0] * li0 + q0.x, oacc[nt][1] * li0 + q0.y);
            float2 o1 = make_float2(oacc[nt][2] * li1 + q1.x, oacc[nt][3] * li1 + q1.y);
            *(float2*)&enf[a0] = o0;
            *(float2*)&enf[a1] = o1;
            cs[nt][0] = o0.x + o1.x;            cs[nt][1] = o0.y + o1.y;
            cq[nt][0] = o0.x * o0.x + o1.x * o1.x;
            cq[nt][1] = o0.y * o0.y + o1.y * o1.y;
        }
    }
    // reduce across the 8 row-pairs of the warp (lane bits 2..4)
#pragma unroll
    for (int nt = 0; nt < 8; nt++)
#pragma unroll
        for (int j = 0; j < 2; j++) {
            cs[nt][j] += __shfl_xor_sync(0xffffffffu, cs[nt][j], 4);
            cs[nt][j] += __shfl_xor_sync(0xffffffffu, cs[nt][j], 8);
            cs[nt][j] += __shfl_xor_sync(0xffffffffu, cs[nt][j], 16);
            cq[nt][j] += __shfl_xor_sync(0xffffffffu, cq[nt][j], 4);
            cq[nt][j] += __shfl_xor_sync(0xffffffffu, cq[nt][j], 8);
            cq[nt][j] += __shfl_xor_sync(0xffffffffu, cq[nt][j], 16);
        }
    __syncthreads();                      // all warps done with Ps -> reuse as scratch
    float* ssm = Ps;                      // [8][64]
    float* sqm = Ps + 512;                // [8][64]
    if (lane < 4) {
#pragma unroll
        for (int nt = 0; nt < 8; nt++) {
            int f = nt * 8 + lane * 2;
            ssm[warp * 64 + f]     = cs[nt][0];
            ssm[warp * 64 + f + 1] = cs[nt][1];
            sqm[warp * 64 + f]     = cq[nt][0];
            sqm[warp * 64 + f + 1] = cq[nt][1];
        }
    }
    __syncthreads();
    if (tid < 64) {
        float s = 0.f, qv = 0.f;
#pragma unroll
        for (int w = 0; w < 8; w++) { s += ssm[w * 64 + tid]; qv += sqm[w * 64 + tid]; }
        size_t o = ((size_t)blockIdx.x * B_ + b) * HF_ + h * 64 + tid;
        psum[o] = s;
        pssq[o] = qv;
    }
}

// ---------------- weff: fold partials -> inv, elementwise weight scale ----------------
__global__ __launch_bounds__(256) void weff_kernel(
    const float* __restrict__ W1,
    const float* __restrict__ psum, const float* __restrict__ pssq,
    float* __restrict__ weff)
{
    const int b = blockIdx.y;
    const int c0 = blockIdx.x * 16;
    const int f = threadIdx.x & 63, cr = threadIdx.x >> 6;
#pragma unroll
    for (int i = 0; i < 4; i++) {
        int c = c0 + i * 4 + cr;
        float s = 0.f, qq = 0.f;
#pragma unroll
        for (int zz = 0; zz < 8; zz++) {
            s  += psum[(size_t)(zz * B_ + b) * HF_ + c];
            qq += pssq[(size_t)(zz * B_ + b) * HF_ + c];
        }
        float mean = s * (1.f / (float)S_);
        float var = qq * (1.f / (float)S_) - mean * mean;
        float iv = rsqrtf(var + EPS_);
        float w = W1[c * F_ + f] + ((c & 63) == f ? 1.f : 0.f);
        weff[(size_t)b * HF_ * F_ + (size_t)c * F_ + f] = w * iv;
    }
}

// ---------------- dense1: split-K x2, K-step 32, 4-stage ring ----------------
// grid (128, 2): blockIdx.y = K half; partial outputs summed in gnorm_final.
__global__ __launch_bounds__(256) void dense1_kernel(
    const float* __restrict__ X, const float* __restrict__ weff,
    float* __restrict__ outp)
{
    extern __shared__ float dsm[];         // 4 stages * 4480 floats (As 64x36 + Ws 32x68)
    const int tid = threadIdx.x;
    const int lane = tid & 31, warp = tid >> 5;
    const int mw = warp & 3;
    const int wn = warp >> 2;
    const int m0 = blockIdx.x * 64;
    const int kbase = blockIdx.y * 512;
    const int b = m0 >> 10;
    const float* Wb = weff + (size_t)b * HF_ * F_;
    float* outh = outp + (size_t)blockIdx.y * (B_ * S_ * F_);

    float acc[4][4];
#pragma unroll
    for (int i = 0; i < 4; i++)
#pragma unroll
        for (int r = 0; r < 4; r++) acc[i][r] = 0.f;

    auto issue = [&](int k0, int stg) {
        float* As = dsm + stg * 4480;
        float* Ws = As + 2304;
#pragma unroll
        for (int t = 0; t < 2; t++) {
            int idx = tid + t * 256;
            int r = idx >> 3, c4 = idx & 7;
            cpasync16(&As[r * 36 + c4 * 4], &X[(size_t)(m0 + r) * HF_ + k0 + c4 * 4]);
        }
#pragma unroll
        for (int t = 0; t < 2; t++) {
            int idx = tid + t * 256;
            int r = idx >> 4, c4 = idx & 15;
            cpasync16(&Ws[r * 68 + c4 * 4], &Wb[(size_t)(k0 + r) * F_ + c4 * 4]);
        }
        cpasync_commit();
    };

    issue(kbase, 0);
    issue(kbase + 32, 1);
    issue(kbase + 64, 2);

    for (int it = 0; it < 16; it++) {
        cpasync_wait2();
        __syncthreads();
        if (it + 3 < 16) issue(kbase + (it + 3) * 32, (it + 3) & 3);
        else cpasync_commit();

        const float* As = dsm + (it & 3) * 4480;
        const float* Ws = As + 2304;
#pragma unroll
        for (int kt = 0; kt < 4; kt++) {
            uint32_t af[4];
            const int rb = mw * 16 + (lane >> 2);
            const int ac = kt * 8 + (lane & 3);
            af[0] = __float_as_uint(As[rb * 36 + ac]);
            af[1] = __float_as_uint(As[(rb + 8) * 36 + ac]);
            af[2] = __float_as_uint(As[rb * 36 + ac + 4]);
            af[3] = __float_as_uint(As[(rb + 8) * 36 + ac + 4]);
            uint32_t bf[4][2];
#pragma unroll
            for (int nt = 0; nt < 4; nt++) {
                int bn = wn * 32 + nt * 8 + (lane >> 2);
                bf[nt][0] = __float_as_uint(Ws[(kt * 8 + (lane & 3)) * 68 + bn]);
                bf[nt][1] = __float_as_uint(Ws[(kt * 8 + (lane & 3) + 4) * 68 + bn]);
            }
#pragma unroll
            for (int nt = 0; nt < 4; nt++)
                mma_tf32(acc[nt], af, bf[nt]);
        }
    }
#pragma unroll
    for (int nt = 0; nt < 4; nt++) {
        int r = m0 + mw * 16 + (lane >> 2);
        int c = wn * 32 + nt * 8 + (lane & 3) * 2;
        *(float2*)&outh[(size_t)r * F_ + c] = make_float2(acc[nt][0], acc[nt][1]);
        *(float2*)&outh[(size_t)(r + 8) * F_ + c] = make_float2(acc[nt][2], acc[nt][3]);
    }
}

// ---------------- final per-channel instance norm (C=64), sums split-K partials ----------------
__global__ __launch_bounds__(1024) void gnorm_final(
    const float* __restrict__ x, float* __restrict__ y)
{
    const int c = blockIdx.x * 32 + threadIdx.x;
    const int b = blockIdx.y;
    const int ty = threadIdx.y;
    const float* x0 = x + (size_t)b * S_ * F_ + c;
    const float* x1 = x0 + (size_t)B_ * S_ * F_;

    float sum = 0.f, ssq = 0.f;
    for (int s = ty; s < S_; s += 32) {
        float v = x0[(size_t)s * F_] + x1[(size_t)s * F_];
        sum += v;
        ssq += v * v;
    }
    __shared__ float rs[32][33], rq[32][33];
    __shared__ float smean[32], sinvs[32];
    rs[ty][threadIdx.x] = sum;
    rq[ty][threadIdx.x] = ssq;
    __syncthreads();
    if (ty == 0) {
        float s = 0.f, qq = 0.f;
#pragma unroll
        for (int i = 0; i < 32; i++) { s += rs[i][threadIdx.x]; qq += rq[i][threadIdx.x]; }
        float mean = s * (1.f / (float)S_);
        float var = qq * (1.f / (float)S_) - mean * mean;
        smean[threadIdx.x] = mean;
        sinvs[threadIdx.x] = rsqrtf(var + EPS_);
    }
    __syncthreads();
    const float mean = smean[threadIdx.x];
    const float inv = sinvs[threadIdx.x];
    float* yb = y + (size_t)b * S_ * F_ + c;
    for (int s = ty; s < S_; s += 32) {
        float v = x0[(size_t)s * F_] + x1[(size_t)s * F_];
        yb[(size_t)s * F_] = (v - mean) * inv;
    }
}

// ---------------- launch ----------------
extern "C" void kernel_launch(void* const* d_in, const int* in_sizes, int n_in,
                              void* d_out, int out_size)
{
    const float* qw = (const float*)d_in[0];
    const float* kw = (const float*)d_in[1];
    const float* vw = (const float*)d_in[2];
    const float* Wq = (const float*)d_in[3];
    const float* bq = (const float*)d_in[4];
    const float* Wk = (const float*)d_in[5];
    const float* bk = (const float*)d_in[6];
    const float* Wv = (const float*)d_in[7];
    const float* bv = (const float*)d_in[8];
    const float* W1 = (const float*)d_in[9];
    float* out = (float*)d_out;

    float *pq, *pk, *pv, *penf, *pout2, *ppsum, *ppssq, *pweff;
    cudaGetSymbolAddress((void**)&pq,    g_q);
    cudaGetSymbolAddress((void**)&pk,    g_k);
    cudaGetSymbolAddress((void**)&pv,    g_v);
    cudaGetSymbolAddress((void**)&penf,  g_enf);
    cudaGetSymbolAddress((void**)&pout2, g_out2);
    cudaGetSymbolAddress((void**)&ppsum, g_psum);
    cudaGetSymbolAddress((void**)&ppssq, g_pssq);
    cudaGetSymbolAddress((void**)&pweff, g_weff);

    static bool attr_done = false;
    if (!attr_done) {
        cudaFuncSetAttribute(qkv_gemm,      cudaFuncAttributeMaxDynamicSharedMemorySize, 75776);
        cudaFuncSetAttribute(attn_tf32,     cudaFuncAttributeMaxDynamicSharedMemorySize, 104448);
        cudaFuncSetAttribute(dense1_kernel, cudaFuncAttributeMaxDynamicSharedMemorySize, 71680);
        attr_done = true;
    }

    qkv_gemm<<<dim3(8, 64, 3), 256, 75776>>>(qw, kw, vw, Wq, Wk, Wv, bq, bk, bv, pq, pk, pv);

    attn_tf32<<<dim3(S_ / 128, H_, B_), 256, 104448>>>(pq, pk, pv, penf, ppsum, ppssq);

    weff_kernel<<<dim3(HF_ / 16, B_), 256>>>(W1, ppsum, ppssq, pweff);

    dense1_kernel<<<dim3((B_ * S_) / 64, 2), 256, 71680>>>(penf, pweff, pout2);

    gnorm_final<<<dim3(F_ / 32, B_), dim3(32, 32)>>>(pout2, out);
}

// round 13
// speedup vs baseline: 1.1130x; 1.0203x over previous
#include <cuda_runtime.h>
#include <cstdint>

#define B_  8
#define S_  1024
#define D_  1024
#define H_  16
#define F_  64
#define HF_ 1024
#define EPS_ 1e-3f

// ---------------- scratch ----------------
__device__ float g_q[B_ * S_ * HF_];
__device__ float g_k[B_ * S_ * HF_];
__device__ float g_v[B_ * S_ * HF_];
__device__ float g_enf[B_ * S_ * HF_];
__device__ float g_out2[2 * B_ * S_ * F_];   // two split-K partials
__device__ float g_psum[8 * B_ * HF_];
__device__ float g_pssq[8 * B_ * HF_];
__device__ float g_weff[B_ * HF_ * F_];

// ---------------- tf32 mma.m16n8k8 ----------------
__device__ __forceinline__ void mma_tf32(float* d, const uint32_t* a, const uint32_t* b) {
    asm volatile(
        "mma.sync.aligned.m16n8k8.row.col.f32.tf32.tf32.f32 "
        "{%0,%1,%2,%3}, {%4,%5,%6,%7}, {%8,%9}, {%0,%1,%2,%3};\n"
        : "+f"(d[0]), "+f"(d[1]), "+f"(d[2]), "+f"(d[3])
        : "r"(a[0]), "r"(a[1]), "r"(a[2]), "r"(a[3]), "r"(b[0]), "r"(b[1]));
}

// ldmatrix x4 on 32-bit data (b16 non-trans trick): reg m of lane t = Mat_m[t/4][t%4] (b32)
__device__ __forceinline__ void ldsm_x4(uint32_t* r, uint32_t addr) {
    asm volatile("ldmatrix.sync.aligned.m8n8.x4.shared.b16 {%0,%1,%2,%3}, [%4];"
        : "=r"(r[0]), "=r"(r[1]), "=r"(r[2]), "=r"(r[3]) : "r"(addr));
}

// ---------------- cp.async helpers ----------------
__device__ __forceinline__ void cpasync16(void* smem, const void* g) {
    uint32_t s = (uint32_t)__cvta_generic_to_shared(smem);
    asm volatile("cp.async.cg.shared.global [%0], [%1], 16;\n" :: "r"(s), "l"(g));
}
__device__ __forceinline__ void cpasync_commit() {
    asm volatile("cp.async.commit_group;\n" ::: "memory");
}
__device__ __forceinline__ void cpasync_wait0() {
    asm volatile("cp.async.wait_group 0;\n" ::: "memory");
}
__device__ __forceinline__ void cpasync_wait2() {
    asm volatile("cp.async.wait_group 2;\n" ::: "memory");
}

// ---------------- fast exp (FMA pipe) ----------------
__device__ __forceinline__ float fexp(float x) {
    float t = fmaxf(x * 1.4426950408889634f, -126.0f);
    int   i = __float2int_rn(t);
    float f = t - (float)i;
    float p = 0.0013333558146428443f;
    p = fmaf(p, f, 0.009618129842126066f);
    p = fmaf(p, f, 0.05550410866482158f);
    p = fmaf(p, f, 0.2402265069591007f);
    p = fmaf(p, f, 0.6931471805599453f);
    p = fmaf(p, f, 1.0f);
    return p * __int_as_float((i + 127) << 23);
}

// ---------------- merged QKV GEMM, 4-stage cp.async ring (unchanged) ----------------
__global__ __launch_bounds__(256) void qkv_gemm(
    const float* __restrict__ A0, const float* __restrict__ A1, const float* __restrict__ A2,
    const float* __restrict__ W0, const float* __restrict__ W1p, const float* __restrict__ W2,
    const float* __restrict__ b0, const float* __restrict__ b1p, const float* __restrict__ b2,
    float* __restrict__ C0, float* __restrict__ C1, float* __restrict__ C2)
{
    extern __shared__ float gsm[];
    const int z = blockIdx.z;
    const float* A    = z == 0 ? A0 : (z == 1 ? A1 : A2);
    const float* W    = z == 0 ? W0 : (z == 1 ? W1p : W2);
    const float* bias = z == 0 ? b0 : (z == 1 ? b1p : b2);
    float*       C    = z == 0 ? C0 : (z == 1 ? C1 : C2);

    const int tid  = threadIdx.x;
    const int lane = tid & 31, warp = tid >> 5;
    const int wm   = warp & 1, wn = warp >> 1;
    const int m0   = blockIdx.y * 128;
    const int n0   = blockIdx.x * 128;

    float acc[4][4][4];
#pragma unroll
    for (int i = 0; i < 4; i++)
#pragma unroll
        for (int j = 0; j < 4; j++)
#pragma unroll
            for (int r = 0; r < 4; r++) acc[i][j][r] = 0.f;

    auto issue = [&](int k0, int stg) {
        float* As = gsm + stg * 4736;
        float* Ws = As + 2560;
#pragma unroll
        for (int t = 0; t < 2; t++) {
            int idx = tid + t * 256;
            int r = idx >> 2, c4 = idx & 3;
            cpasync16(&As[r * 20 + c4 * 4], &A[(size_t)(m0 + r) * D_ + k0 + c4 * 4]);
        }
#pragma unroll
        for (int t = 0; t < 2; t++) {
            int idx = tid + t * 256;
            int r = idx >> 5, c8 = idx & 31;
            cpasync16(&Ws[r * 136 + c8 * 4], &W[(size_t)(k0 + r) * HF_ + n0 + c8 * 4]);
        }
        cpasync_commit();
    };

    issue(0, 0);
    issue(16, 1);
    issue(32, 2);

    for (int it = 0; it < 64; it++) {
        cpasync_wait2();
        __syncthreads();
        if (it + 3 < 64) issue((it + 3) * 16, (it + 3) & 3);
        else cpasync_commit();

        const float* As = gsm + (it & 3) * 4736;
        const float* Ws = As + 2560;
#pragma unroll
        for (int kt = 0; kt < 2; kt++) {
            uint32_t af[4][4];
            const int ar = lane >> 2, ac = kt * 8 + (lane & 3);
#pragma unroll
            for (int mt = 0; mt < 4; mt++) {
                int rb = wm * 64 + mt * 16 + ar;
                af[mt][0] = __float_as_uint(As[rb * 20 + ac]);
                af[mt][1] = __float_as_uint(As[(rb + 8) * 20 + ac]);
                af[mt][2] = __float_as_uint(As[rb * 20 + ac + 4]);
                af[mt][3] = __float_as_uint(As[(rb + 8) * 20 + ac + 4]);
            }
            uint32_t bf[4][2];
#pragma unroll
            for (int nt = 0; nt < 4; nt++) {
                int bn = wn * 32 + nt * 8 + (lane >> 2);
                bf[nt][0] = __float_as_uint(Ws[(kt * 8 + (lane & 3)) * 136 + bn]);
                bf[nt][1] = __float_as_uint(Ws[(kt * 8 + (lane & 3) + 4) * 136 + bn]);
            }
#pragma unroll
            for (int mt = 0; mt < 4; mt++)
#pragma unroll
                for (int nt = 0; nt < 4; nt++)
                    mma_tf32(acc[mt][nt], af[mt], bf[nt]);
        }
    }

#pragma unroll
    for (int mt = 0; mt < 4; mt++) {
#pragma unroll
        for (int nt = 0; nt < 4; nt++) {
            int r = m0 + wm * 64 + mt * 16 + (lane >> 2);
            int c = n0 + wn * 32 + nt * 8 + (lane & 3) * 2;
            float bv0 = bias[c], bv1 = bias[c + 1];
            *(float2*)&C[(size_t)r * HF_ + c] =
                make_float2(acc[mt][nt][0] + bv0, acc[mt][nt][1] + bv1);
            *(float2*)&C[(size_t)(r + 8) * HF_ + c] =
                make_float2(acc[mt][nt][2] + bv0, acc[mt][nt][3] + bv1);
        }
    }
}

// ---------------- flash attention + fused stats, ldmatrix fragment loads ----------------
#define LD 68
__global__ __launch_bounds__(256, 2) void attn_tf32(
    const float* __restrict__ q, const float* __restrict__ k,
    const float* __restrict__ v, float* __restrict__ enf,
    float* __restrict__ psum, float* __restrict__ pssq)
{
    extern __shared__ float sm[];
    float* Ks = sm;                    // [2][64*LD]
    float* Vs = Ks + 2 * 64 * LD;      // [2][64*LD]
    float* Ps = Vs + 2 * 64 * LD;      // [128*LD]

    const int b = blockIdx.z, h = blockIdx.y, i0 = blockIdx.x * 128;
    const int tid = threadIdx.x, lane = tid & 31, warp = tid >> 5;
    const int r0 = warp * 16 + (lane >> 2), r1 = r0 + 8;
    const int lt = lane & 3;

    const uint32_t smb = (uint32_t)__cvta_generic_to_shared(sm);
    const uint32_t KsA = smb;
    const uint32_t PsA = smb + 4u * (4 * 64 * LD);

    // LDSM address bases (thread-constant row/col offsets)
    // K B-frags: mat order {bf0(nt=2g), bf1(nt=2g), bf0(nt=2g+1), bf1(nt=2g+1)}
    const uint32_t jrK = (((uint32_t)lane >> 4) & 1) * 8 + (lane & 7);
    const uint32_t cK  = (((uint32_t)lane >> 3) & 1) * 4;
    const uint32_t koff = (jrK * LD + cK) * 4;
    // P A-frags: mat order {af0, af1, af2, af3}
    const uint32_t jrP = warp * 16 + (((uint32_t)lane >> 3) & 1) * 8 + (lane & 7);
    const uint32_t cP  = (((uint32_t)lane >> 4) & 1) * 4;
    const uint32_t paddr0 = PsA + (jrP * LD + cP) * 4;

    auto issue = [&](int c0, int stg) {
        const float* kb = k + (size_t)(b * S_ + c0) * HF_ + h * 64;
        const float* vb = v + (size_t)(b * S_ + c0) * HF_ + h * 64;
        float* Kd = Ks + stg * 64 * LD;
        float* Vd = Vs + stg * 64 * LD;
#pragma unroll
        for (int t = 0; t < 4; t++) {
            int idx = tid + t * 256;
            int r = idx >> 4, c4 = idx & 15;
            cpasync16(&Kd[r * LD + c4 * 4], kb + (size_t)r * HF_ + c4 * 4);
            cpasync16(&Vd[r * LD + c4 * 4], vb + (size_t)r * HF_ + c4 * 4);
        }
        cpasync_commit();
    };

    issue(0, 0);

    for (int idx = tid; idx < 128 * 16; idx += 256) {
        int r = idx >> 4, c4 = idx & 15;
        float4 vq = *(const float4*)&q[(size_t)(b * S_ + i0 + r) * HF_ + h * 64 + c4 * 4];
        vq.x *= 0.125f; vq.y *= 0.125f; vq.z *= 0.125f; vq.w *= 0.125f;
        *(float4*)&Ps[r * LD + c4 * 4] = vq;
    }
    __syncthreads();

    uint32_t qf[8][4];
#pragma unroll
    for (int kt = 0; kt < 8; kt++)
        ldsm_x4(qf[kt], paddr0 + kt * 8 * 4);

    float lrun0 = 0.f, lrun1 = 0.f;
    float oacc[8][4];
#pragma unroll
    for (int i = 0; i < 8; i++)
#pragma unroll
        for (int j = 0; j < 4; j++) oacc[i][j] = 0.f;

    for (int it = 0; it < 16; it++) {
        cpasync_wait0();
        __syncthreads();
        if (it < 15) issue((it + 1) * 64, (it + 1) & 1);

        const uint32_t kbufA = KsA + (it & 1) * (64 * LD * 4) + koff;
        const float* Vc = Vs + (it & 1) * 64 * LD;

        // ---- S = (Q*0.125) K^T : K fragments via LDSM ----
        float sacc[8][4];
#pragma unroll
        for (int i = 0; i < 8; i++)
#pragma unroll
            for (int j = 0; j < 4; j++) sacc[i][j] = 0.f;
#pragma unroll
        for (int kt = 0; kt < 8; kt++) {
#pragma unroll
            for (int g = 0; g < 4; g++) {
                uint32_t bm[4];
                ldsm_x4(bm, kbufA + (g * 16 * LD + kt * 8) * 4);
                mma_tf32(sacc[2 * g],     qf[kt], bm);
                mma_tf32(sacc[2 * g + 1], qf[kt], bm + 2);
            }
        }

        // ---- maxless softmax: P = exp(S); l += rowsum(P) ----
        float sum0 = 0.f, sum1 = 0.f;
#pragma unroll
        for (int nt = 0; nt < 8; nt++) {
            float e0 = fexp(sacc[nt][0]);
            float e1 = fexp(sacc[nt][1]);
            float e2 = fexp(sacc[nt][2]);
            float e3 = fexp(sacc[nt][3]);
            sum0 += e0 + e1; sum1 += e2 + e3;
            int c = nt * 8 + lt * 2;
            *(float2*)&Ps[r0 * LD + c] = make_float2(e0, e1);
            *(float2*)&Ps[r1 * LD + c] = make_float2(e2, e3);
        }
        sum0 += __shfl_xor_sync(0xffffffffu, sum0, 1);
        sum0 += __shfl_xor_sync(0xffffffffu, sum0, 2);
        sum1 += __shfl_xor_sync(0xffffffffu, sum1, 1);
        sum1 += __shfl_xor_sync(0xffffffffu, sum1, 2);
        lrun0 += sum0;
        lrun1 += sum1;
        __syncwarp();

        // ---- O += P @ V : P A-frags via LDSM, V scalar ----
#pragma unroll
        for (int kt = 0; kt < 8; kt++) {
            uint32_t af[4];
            ldsm_x4(af, paddr0 + kt * 8 * 4);
#pragma unroll
            for (int nt = 0; nt < 8; nt++) {
                uint32_t bf[2];
                int fn = nt * 8 + (lane >> 2);
                bf[0] = __float_as_uint(Vc[(kt * 8 + lt) * LD + fn]);
                bf[1] = __float_as_uint(Vc[(kt * 8 + lt + 4) * LD + fn]);
                mma_tf32(oacc[nt], af, bf);
            }
        }
    }

    // ---- epilogue: O/l + q residual, fused per-channel partial stats ----
    float cs[8][2], cq[8][2];
    {
        float li0 = 1.f / lrun0, li1 = 1.f / lrun1;
#pragma unroll
        for (int nt = 0; nt < 8; nt++) {
            int c = nt * 8 + lt * 2;
            size_t a0 = (size_t)(b * S_ + i0 + r0) * HF_ + h * 64 + c;
            size_t a1 = (size_t)(b * S_ + i0 + r1) * HF_ + h * 64 + c;
            float2 q0 = *(const float2*)&q[a0];
            float2 q1 = *(const float2*)&q[a1];
            float2 o0 = make_float2(oacc[nt][0] * li0 + q0.x, oacc[nt][1] * li0 + q0.y);
            float2 o1 = make_float2(oacc[nt][2] * li1 + q1.x, oacc[nt][3] * li1 + q1.y);
            *(float2*)&enf[a0] = o0;
            *(float2*)&enf[a1] = o1;
            cs[nt][0] = o0.x + o1.x;            cs[nt][1] = o0.y + o1.y;
            cq[nt][0] = o0.x * o0.x + o1.x * o1.x;
            cq[nt][1] = o0.y * o0.y + o1.y * o1.y;
        }
    }
#pragma unroll
    for (int nt = 0; nt < 8; nt++)
#pragma unroll
        for (int j = 0; j < 2; j++) {
            cs[nt][j] += __shfl_xor_sync(0xffffffffu, cs[nt][j], 4);
            cs[nt][j] += __shfl_xor_sync(0xffffffffu, cs[nt][j], 8);
            cs[nt][j] += __shfl_xor_sync(0xffffffffu, cs[nt][j], 16);
            cq[nt][j] += __shfl_xor_sync(0xffffffffu, cq[nt][j], 4);
            cq[nt][j] += __shfl_xor_sync(0xffffffffu, cq[nt][j], 8);
            cq[nt][j] += __shfl_xor_sync(0xffffffffu, cq[nt][j], 16);
        }
    __syncthreads();
    float* ssm = Ps;
    float* sqm = Ps + 512;
    if (lane < 4) {
#pragma unroll
        for (int nt = 0; nt < 8; nt++) {
            int f = nt * 8 + lane * 2;
            ssm[warp * 64 + f]     = cs[nt][0];
            ssm[warp * 64 + f + 1] = cs[nt][1];
            sqm[warp * 64 + f]     = cq[nt][0];
            sqm[warp * 64 + f + 1] = cq[nt][1];
        }
    }
    __syncthreads();
    if (tid < 64) {
        float s = 0.f, qv = 0.f;
#pragma unroll
        for (int w = 0; w < 8; w++) { s += ssm[w * 64 + tid]; qv += sqm[w * 64 + tid]; }
        size_t o = ((size_t)blockIdx.x * B_ + b) * HF_ + h * 64 + tid;
        psum[o] = s;
        pssq[o] = qv;
    }
}

// ---------------- weff: fold partials -> inv, elementwise weight scale ----------------
__global__ __launch_bounds__(256) void weff_kernel(
    const float* __restrict__ W1,
    const float* __restrict__ psum, const float* __restrict__ pssq,
    float* __restrict__ weff)
{
    const int b = blockIdx.y;
    const int c0 = blockIdx.x * 16;
    const int f = threadIdx.x & 63, cr = threadIdx.x >> 6;
#pragma unroll
    for (int i = 0; i < 4; i++) {
        int c = c0 + i * 4 + cr;
        float s = 0.f, qq = 0.f;
#pragma unroll
        for (int zz = 0; zz < 8; zz++) {
            s  += psum[(size_t)(zz * B_ + b) * HF_ + c];
            qq += pssq[(size_t)(zz * B_ + b) * HF_ + c];
        }
        float mean = s * (1.f / (float)S_);
        float var = qq * (1.f / (float)S_) - mean * mean;
        float iv = rsqrtf(var + EPS_);
        float w = W1[c * F_ + f] + ((c & 63) == f ? 1.f : 0.f);
        weff[(size_t)b * HF_ * F_ + (size_t)c * F_ + f] = w * iv;
    }
}

// ---------------- dense1: split-K x2, K-step 32, 4-stage ring ----------------
__global__ __launch_bounds__(256) void dense1_kernel(
    const float* __restrict__ X, const float* __restrict__ weff,
    float* __restrict__ outp)
{
    extern __shared__ float dsm[];
    const int tid = threadIdx.x;
    const int lane = tid & 31, warp = tid >> 5;
    const int mw = warp & 3;
    const int wn = warp >> 2;
    const int m0 = blockIdx.x * 64;
    const int kbase = blockIdx.y * 512;
    const int b = m0 >> 10;
    const float* Wb = weff + (size_t)b * HF_ * F_;
    float* outh = outp + (size_t)blockIdx.y * (B_ * S_ * F_);

    float acc[4][4];
#pragma unroll
    for (int i = 0; i < 4; i++)
#pragma unroll
        for (int r = 0; r < 4; r++) acc[i][r] = 0.f;

    auto issue = [&](int k0, int stg) {
        float* As = dsm + stg * 4480;
        float* Ws = As + 2304;
#pragma unroll
        for (int t = 0; t < 2; t++) {
            int idx = tid + t * 256;
            int r = idx >> 3, c4 = idx & 7;
            cpasync16(&As[r * 36 + c4 * 4], &X[(size_t)(m0 + r) * HF_ + k0 + c4 * 4]);
        }
#pragma unroll
        for (int t = 0; t < 2; t++) {
            int idx = tid + t * 256;
            int r = idx >> 4, c4 = idx & 15;
            cpasync16(&Ws[r * 68 + c4 * 4], &Wb[(size_t)(k0 + r) * F_ + c4 * 4]);
        }
        cpasync_commit();
    };

    issue(kbase, 0);
    issue(kbase + 32, 1);
    issue(kbase + 64, 2);

    for (int it = 0; it < 16; it++) {
        cpasync_wait2();
        __syncthreads();
        if (it + 3 < 16) issue(kbase + (it + 3) * 32, (it + 3) & 3);
        else cpasync_commit();

        const float* As = dsm + (it & 3) * 4480;
        const float* Ws = As + 2304;
#pragma unroll
        for (int kt = 0; kt < 4; kt++) {
            uint32_t af[4];
            const int rb = mw * 16 + (lane >> 2);
            const int ac = kt * 8 + (lane & 3);
            af[0] = __float_as_uint(As[rb * 36 + ac]);
            af[1] = __float_as_uint(As[(rb + 8) * 36 + ac]);
            af[2] = __float_as_uint(As[rb * 36 + ac + 4]);
            af[3] = __float_as_uint(As[(rb + 8) * 36 + ac + 4]);
            uint32_t bf[4][2];
#pragma unroll
            for (int nt = 0; nt < 4; nt++) {
                int bn = wn * 32 + nt * 8 + (lane >> 2);
                bf[nt][0] = __float_as_uint(Ws[(kt * 8 + (lane & 3)) * 68 + bn]);
                bf[nt][1] = __float_as_uint(Ws[(kt * 8 + (lane & 3) + 4) * 68 + bn]);
            }
#pragma unroll
            for (int nt = 0; nt < 4; nt++)
                mma_tf32(acc[nt], af, bf[nt]);
        }
    }
#pragma unroll
    for (int nt = 0; nt < 4; nt++) {
        int r = m0 + mw * 16 + (lane >> 2);
        int c = wn * 32 + nt * 8 + (lane & 3) * 2;
        *(float2*)&outh[(size_t)r * F_ + c] = make_float2(acc[nt][0], acc[nt][1]);
        *(float2*)&outh[(size_t)(r + 8) * F_ + c] = make_float2(acc[nt][2], acc[nt][3]);
    }
}

// ---------------- final per-channel instance norm (C=64), sums split-K partials ----------------
__global__ __launch_bounds__(1024) void gnorm_final(
    const float* __restrict__ x, float* __restrict__ y)
{
    const int c = blockIdx.x * 32 + threadIdx.x;
    const int b = blockIdx.y;
    const int ty = threadIdx.y;
    const float* x0 = x + (size_t)b * S_ * F_ + c;
    const float* x1 = x0 + (size_t)B_ * S_ * F_;

    float sum = 0.f, ssq = 0.f;
    for (int s = ty; s < S_; s += 32) {
        float v = x0[(size_t)s * F_] + x1[(size_t)s * F_];
        sum += v;
        ssq += v * v;
    }
    __shared__ float rs[32][33], rq[32][33];
    __shared__ float smean[32], sinvs[32];
    rs[ty][threadIdx.x] = sum;
    rq[ty][threadIdx.x] = ssq;
    __syncthreads();
    if (ty == 0) {
        float s = 0.f, qq = 0.f;
#pragma unroll
        for (int i = 0; i < 32; i++) { s += rs[i][threadIdx.x]; qq += rq[i][threadIdx.x]; }
        float mean = s * (1.f / (float)S_);
        float var = qq * (1.f / (float)S_) - mean * mean;
        smean[threadIdx.x] = mean;
        sinvs[threadIdx.x] = rsqrtf(var + EPS_);
    }
    __syncthreads();
    const float mean = smean[threadIdx.x];
    const float inv = sinvs[threadIdx.x];
    float* yb = y + (size_t)b * S_ * F_ + c;
    for (int s = ty; s < S_; s += 32) {
        float v = x0[(size_t)s * F_] + x1[(size_t)s * F_];
        yb[(size_t)s * F_] = (v - mean) * inv;
    }
}

// ---------------- launch ----------------
extern "C" void kernel_launch(void* const* d_in, const int* in_sizes, int n_in,
                              void* d_out, int out_size)
{
    const float* qw = (const float*)d_in[0];
    const float* kw = (const float*)d_in[1];
    const float* vw = (const float*)d_in[2];
    const float* Wq = (const float*)d_in[3];
    const float* bq = (const float*)d_in[4];
    const float* Wk = (const float*)d_in[5];
    const float* bk = (const float*)d_in[6];
    const float* Wv = (const float*)d_in[7];
    const float* bv = (const float*)d_in[8];
    const float* W1 = (const float*)d_in[9];
    float* out = (float*)d_out;

    float *pq, *pk, *pv, *penf, *pout2, *ppsum, *ppssq, *pweff;
    cudaGetSymbolAddress((void**)&pq,    g_q);
    cudaGetSymbolAddress((void**)&pk,    g_k);
    cudaGetSymbolAddress((void**)&pv,    g_v);
    cudaGetSymbolAddress((void**)&penf,  g_enf);
    cudaGetSymbolAddress((void**)&pout2, g_out2);
    cudaGetSymbolAddress((void**)&ppsum, g_psum);
    cudaGetSymbolAddress((void**)&ppssq, g_pssq);
    cudaGetSymbolAddress((void**)&pweff, g_weff);

    static bool attr_done = false;
    if (!attr_done) {
        cudaFuncSetAttribute(qkv_gemm,      cudaFuncAttributeMaxDynamicSharedMemorySize, 75776);
        cudaFuncSetAttribute(attn_tf32,     cudaFuncAttributeMaxDynamicSharedMemorySize, 104448);
        cudaFuncSetAttribute(dense1_kernel, cudaFuncAttributeMaxDynamicSharedMemorySize, 71680);
        attr_done = true;
    }

    qkv_gemm<<<dim3(8, 64, 3), 256, 75776>>>(qw, kw, vw, Wq, Wk, Wv, bq, bk, bv, pq, pk, pv);

    attn_tf32<<<dim3(S_ / 128, H_, B_), 256, 104448>>>(pq, pk, pv, penf, ppsum, ppssq);

    weff_kernel<<<dim3(HF_ / 16, B_), 256>>>(W1, ppsum, ppssq, pweff);

    dense1_kernel<<<dim3((B_ * S_) / 64, 2), 256, 71680>>>(penf, pweff, pout2);

    gnorm_final<<<dim3(F_ / 32, B_), dim3(32, 32)>>>(pout2, out);
}

// round 14
// speedup vs baseline: 1.1334x; 1.0184x over previous
#include <cuda_runtime.h>
#include <cstdint>

#define B_  8
#define S_  1024
#define D_  1024
#define H_  16
#define F_  64
#define HF_ 1024
#define EPS_ 1e-3f

// ---------------- scratch ----------------
__device__ float g_q[B_ * S_ * HF_];
__device__ float g_k[B_ * S_ * HF_];
__device__ float g_v[B_ * S_ * HF_];
__device__ float g_enf[B_ * S_ * HF_];
__device__ float g_out2[2 * B_ * S_ * F_];   // two split-K partials
__device__ float g_psum[8 * B_ * HF_];
__device__ float g_pssq[8 * B_ * HF_];
__device__ float g_weff[B_ * HF_ * F_];

// ---------------- tf32 mma.m16n8k8 ----------------
__device__ __forceinline__ void mma_tf32(float* d, const uint32_t* a, const uint32_t* b) {
    asm volatile(
        "mma.sync.aligned.m16n8k8.row.col.f32.tf32.tf32.f32 "
        "{%0,%1,%2,%3}, {%4,%5,%6,%7}, {%8,%9}, {%0,%1,%2,%3};\n"
        : "+f"(d[0]), "+f"(d[1]), "+f"(d[2]), "+f"(d[3])
        : "r"(a[0]), "r"(a[1]), "r"(a[2]), "r"(a[3]), "r"(b[0]), "r"(b[1]));
}

// ldmatrix x4 on 32-bit data (b16 non-trans trick): reg m of lane t = Mat_m[t/4][t%4] (b32)
__device__ __forceinline__ void ldsm_x4(uint32_t* r, uint32_t addr) {
    asm volatile("ldmatrix.sync.aligned.m8n8.x4.shared.b16 {%0,%1,%2,%3}, [%4];"
        : "=r"(r[0]), "=r"(r[1]), "=r"(r[2]), "=r"(r[3]) : "r"(addr));
}

// ---------------- cp.async helpers ----------------
__device__ __forceinline__ void cpasync16(void* smem, const void* g) {
    uint32_t s = (uint32_t)__cvta_generic_to_shared(smem);
    asm volatile("cp.async.cg.shared.global [%0], [%1], 16;\n" :: "r"(s), "l"(g));
}
__device__ __forceinline__ void cpasync_commit() {
    asm volatile("cp.async.commit_group;\n" ::: "memory");
}
__device__ __forceinline__ void cpasync_wait0() {
    asm volatile("cp.async.wait_group 0;\n" ::: "memory");
}
__device__ __forceinline__ void cpasync_wait2() {
    asm volatile("cp.async.wait_group 2;\n" ::: "memory");
}

// ---------------- fast exp (FMA pipe) ----------------
__device__ __forceinline__ float fexp(float x) {
    float t = fmaxf(x * 1.4426950408889634f, -126.0f);
    int   i = __float2int_rn(t);
    float f = t - (float)i;
    float p = 0.0013333558146428443f;
    p = fmaf(p, f, 0.009618129842126066f);
    p = fmaf(p, f, 0.05550410866482158f);
    p = fmaf(p, f, 0.2402265069591007f);
    p = fmaf(p, f, 0.6931471805599453f);
    p = fmaf(p, f, 1.0f);
    return p * __int_as_float((i + 127) << 23);
}

// ---------------- merged QKV GEMM, 4-stage ring, LDSM A-frags ----------------
__global__ __launch_bounds__(256) void qkv_gemm(
    const float* __restrict__ A0, const float* __restrict__ A1, const float* __restrict__ A2,
    const float* __restrict__ W0, const float* __restrict__ W1p, const float* __restrict__ W2,
    const float* __restrict__ b0, const float* __restrict__ b1p, const float* __restrict__ b2,
    float* __restrict__ C0, float* __restrict__ C1, float* __restrict__ C2)
{
    extern __shared__ float gsm[];
    const int z = blockIdx.z;
    const float* A    = z == 0 ? A0 : (z == 1 ? A1 : A2);
    const float* W    = z == 0 ? W0 : (z == 1 ? W1p : W2);
    const float* bias = z == 0 ? b0 : (z == 1 ? b1p : b2);
    float*       C    = z == 0 ? C0 : (z == 1 ? C1 : C2);

    const int tid  = threadIdx.x;
    const int lane = tid & 31, warp = tid >> 5;
    const int wm   = warp & 1, wn = warp >> 1;
    const int m0   = blockIdx.y * 128;
    const int n0   = blockIdx.x * 128;

    const uint32_t gsmA = (uint32_t)__cvta_generic_to_shared(gsm);
    // LDSM A-frag thread offset: mat = lane>>3; row = wm*64 + (mat&1)*8 + (lane&7); col = (mat>>1)*4
    const uint32_t mA = (uint32_t)lane >> 3;
    const uint32_t aoff = ((wm * 64 + (mA & 1) * 8 + (lane & 7)) * 20 + (mA >> 1) * 4) * 4;

    float acc[4][4][4];
#pragma unroll
    for (int i = 0; i < 4; i++)
#pragma unroll
        for (int j = 0; j < 4; j++)
#pragma unroll
            for (int r = 0; r < 4; r++) acc[i][j][r] = 0.f;

    auto issue = [&](int k0, int stg) {
        float* As = gsm + stg * 4736;
        float* Ws = As + 2560;
#pragma unroll
        for (int t = 0; t < 2; t++) {
            int idx = tid + t * 256;
            int r = idx >> 2, c4 = idx & 3;
            cpasync16(&As[r * 20 + c4 * 4], &A[(size_t)(m0 + r) * D_ + k0 + c4 * 4]);
        }
#pragma unroll
        for (int t = 0; t < 2; t++) {
            int idx = tid + t * 256;
            int r = idx >> 5, c8 = idx & 31;
            cpasync16(&Ws[r * 136 + c8 * 4], &W[(size_t)(k0 + r) * HF_ + n0 + c8 * 4]);
        }
        cpasync_commit();
    };

    issue(0, 0);
    issue(16, 1);
    issue(32, 2);

    for (int it = 0; it < 64; it++) {
        cpasync_wait2();
        __syncthreads();
        if (it + 3 < 64) issue((it + 3) * 16, (it + 3) & 3);
        else cpasync_commit();

        const uint32_t asA = gsmA + (uint32_t)((it & 3) * 4736) * 4 + aoff;
        const float* Ws = gsm + (it & 3) * 4736 + 2560;
#pragma unroll
        for (int kt = 0; kt < 2; kt++) {
            uint32_t af[4][4];
#pragma unroll
            for (int mt = 0; mt < 4; mt++)
                ldsm_x4(af[mt], asA + (uint32_t)(mt * 320 + kt * 8) * 4);
            uint32_t bf[4][2];
#pragma unroll
            for (int nt = 0; nt < 4; nt++) {
                int bn = wn * 32 + nt * 8 + (lane >> 2);
                bf[nt][0] = __float_as_uint(Ws[(kt * 8 + (lane & 3)) * 136 + bn]);
                bf[nt][1] = __float_as_uint(Ws[(kt * 8 + (lane & 3) + 4) * 136 + bn]);
            }
#pragma unroll
            for (int mt = 0; mt < 4; mt++)
#pragma unroll
                for (int nt = 0; nt < 4; nt++)
                    mma_tf32(acc[mt][nt], af[mt], bf[nt]);
        }
    }

#pragma unroll
    for (int mt = 0; mt < 4; mt++) {
#pragma unroll
        for (int nt = 0; nt < 4; nt++) {
            int r = m0 + wm * 64 + mt * 16 + (lane >> 2);
            int c = n0 + wn * 32 + nt * 8 + (lane & 3) * 2;
            float bv0 = bias[c], bv1 = bias[c + 1];
            *(float2*)&C[(size_t)r * HF_ + c] =
                make_float2(acc[mt][nt][0] + bv0, acc[mt][nt][1] + bv1);
            *(float2*)&C[(size_t)(r + 8) * HF_ + c] =
                make_float2(acc[mt][nt][2] + bv0, acc[mt][nt][3] + bv1);
        }
    }
}

// ---------------- flash attention + fused stats, LDSM fragment loads ----------------
#define LD 68
__global__ __launch_bounds__(256, 2) void attn_tf32(
    const float* __restrict__ q, const float* __restrict__ k,
    const float* __restrict__ v, float* __restrict__ enf,
    float* __restrict__ psum, float* __restrict__ pssq)
{
    extern __shared__ float sm[];
    float* Ks = sm;                    // [2][64*LD]
    float* Vs = Ks + 2 * 64 * LD;      // [2][64*LD]
    float* Ps = Vs + 2 * 64 * LD;      // [128*LD]

    const int b = blockIdx.z, h = blockIdx.y, i0 = blockIdx.x * 128;
    const int tid = threadIdx.x, lane = tid & 31, warp = tid >> 5;
    const int r0 = warp * 16 + (lane >> 2), r1 = r0 + 8;
    const int lt = lane & 3;

    const uint32_t smb = (uint32_t)__cvta_generic_to_shared(sm);
    const uint32_t KsA = smb;
    const uint32_t PsA = smb + 4u * (4 * 64 * LD);

    const uint32_t jrK = (((uint32_t)lane >> 4) & 1) * 8 + (lane & 7);
    const uint32_t cK  = (((uint32_t)lane >> 3) & 1) * 4;
    const uint32_t koff = (jrK * LD + cK) * 4;
    const uint32_t jrP = warp * 16 + (((uint32_t)lane >> 3) & 1) * 8 + (lane & 7);
    const uint32_t cP  = (((uint32_t)lane >> 4) & 1) * 4;
    const uint32_t paddr0 = PsA + (jrP * LD + cP) * 4;

    auto issue = [&](int c0, int stg) {
        const float* kb = k + (size_t)(b * S_ + c0) * HF_ + h * 64;
        const float* vb = v + (size_t)(b * S_ + c0) * HF_ + h * 64;
        float* Kd = Ks + stg * 64 * LD;
        float* Vd = Vs + stg * 64 * LD;
#pragma unroll
        for (int t = 0; t < 4; t++) {
            int idx = tid + t * 256;
            int r = idx >> 4, c4 = idx & 15;
            cpasync16(&Kd[r * LD + c4 * 4], kb + (size_t)r * HF_ + c4 * 4);
            cpasync16(&Vd[r * LD + c4 * 4], vb + (size_t)r * HF_ + c4 * 4);
        }
        cpasync_commit();
    };

    issue(0, 0);

    for (int idx = tid; idx < 128 * 16; idx += 256) {
        int r = idx >> 4, c4 = idx & 15;
        float4 vq = *(const float4*)&q[(size_t)(b * S_ + i0 + r) * HF_ + h * 64 + c4 * 4];
        vq.x *= 0.125f; vq.y *= 0.125f; vq.z *= 0.125f; vq.w *= 0.125f;
        *(float4*)&Ps[r * LD + c4 * 4] = vq;
    }
    __syncthreads();

    uint32_t qf[8][4];
#pragma unroll
    for (int kt = 0; kt < 8; kt++)
        ldsm_x4(qf[kt], paddr0 + kt * 8 * 4);

    float lrun0 = 0.f, lrun1 = 0.f;
    float oacc[8][4];
#pragma unroll
    for (int i = 0; i < 8; i++)
#pragma unroll
        for (int j = 0; j < 4; j++) oacc[i][j] = 0.f;

    for (int it = 0; it < 16; it++) {
        cpasync_wait0();
        __syncthreads();
        if (it < 15) issue((it + 1) * 64, (it + 1) & 1);

        const uint32_t kbufA = KsA + (it & 1) * (64 * LD * 4) + koff;
        const float* Vc = Vs + (it & 1) * 64 * LD;

        float sacc[8][4];
#pragma unroll
        for (int i = 0; i < 8; i++)
#pragma unroll
            for (int j = 0; j < 4; j++) sacc[i][j] = 0.f;
#pragma unroll
        for (int kt = 0; kt < 8; kt++) {
#pragma unroll
            for (int g = 0; g < 4; g++) {
                uint32_t bm[4];
                ldsm_x4(bm, kbufA + (g * 16 * LD + kt * 8) * 4);
                mma_tf32(sacc[2 * g],     qf[kt], bm);
                mma_tf32(sacc[2 * g + 1], qf[kt], bm + 2);
            }
        }

        float sum0 = 0.f, sum1 = 0.f;
#pragma unroll
        for (int nt = 0; nt < 8; nt++) {
            float e0 = fexp(sacc[nt][0]);
            float e1 = fexp(sacc[nt][1]);
            float e2 = fexp(sacc[nt][2]);
            float e3 = fexp(sacc[nt][3]);
            sum0 += e0 + e1; sum1 += e2 + e3;
            int c = nt * 8 + lt * 2;
            *(float2*)&Ps[r0 * LD + c] = make_float2(e0, e1);
            *(float2*)&Ps[r1 * LD + c] = make_float2(e2, e3);
        }
        sum0 += __shfl_xor_sync(0xffffffffu, sum0, 1);
        sum0 += __shfl_xor_sync(0xffffffffu, sum0, 2);
        sum1 += __shfl_xor_sync(0xffffffffu, sum1, 1);
        sum1 += __shfl_xor_sync(0xffffffffu, sum1, 2);
        lrun0 += sum0;
        lrun1 += sum1;
        __syncwarp();

#pragma unroll
        for (int kt = 0; kt < 8; kt++) {
            uint32_t af[4];
            ldsm_x4(af, paddr0 + kt * 8 * 4);
#pragma unroll
            for (int nt = 0; nt < 8; nt++) {
                uint32_t bf[2];
                int fn = nt * 8 + (lane >> 2);
                bf[0] = __float_as_uint(Vc[(kt * 8 + lt) * LD + fn]);
                bf[1] = __float_as_uint(Vc[(kt * 8 + lt + 4) * LD + fn]);
                mma_tf32(oacc[nt], af, bf);
            }
        }
    }

    float cs[8][2], cq[8][2];
    {
        float li0 = 1.f / lrun0, li1 = 1.f / lrun1;
#pragma unroll
        for (int nt = 0; nt < 8; nt++) {
            int c = nt * 8 + lt * 2;
            size_t a0 = (size_t)(b * S_ + i0 + r0) * HF_ + h * 64 + c;
            size_t a1 = (size_t)(b * S_ + i0 + r1) * HF_ + h * 64 + c;
            float2 q0 = *(const float2*)&q[a0];
            float2 q1 = *(const float2*)&q[a1];
            float2 o0 = make_float2(oacc[nt][0] * li0 + q0.x, oacc[nt][1] * li0 + q0.y);
            float2 o1 = make_float2(oacc[nt][2] * li1 + q1.x, oacc[nt][3] * li1 + q1.y);
            *(float2*)&enf[a0] = o0;
            *(float2*)&enf[a1] = o1;
            cs[nt][0] = o0.x + o1.x;            cs[nt][1] = o0.y + o1.y;
            cq[nt][0] = o0.x * o0.x + o1.x * o1.x;
            cq[nt][1] = o0.y * o0.y + o1.y * o1.y;
        }
    }
#pragma unroll
    for (int nt = 0; nt < 8; nt++)
#pragma unroll
        for (int j = 0; j < 2; j++) {
            cs[nt][j] += __shfl_xor_sync(0xffffffffu, cs[nt][j], 4);
            cs[nt][j] += __shfl_xor_sync(0xffffffffu, cs[nt][j], 8);
            cs[nt][j] += __shfl_xor_sync(0xffffffffu, cs[nt][j], 16);
            cq[nt][j] += __shfl_xor_sync(0xffffffffu, cq[nt][j], 4);
            cq[nt][j] += __shfl_xor_sync(0xffffffffu, cq[nt][j], 8);
            cq[nt][j] += __shfl_xor_sync(0xffffffffu, cq[nt][j], 16);
        }
    __syncthreads();
    float* ssm = Ps;
    float* sqm = Ps + 512;
    if (lane < 4) {
#pragma unroll
        for (int nt = 0; nt < 8; nt++) {
            int f = nt * 8 + lane * 2;
            ssm[warp * 64 + f]     = cs[nt][0];
            ssm[warp * 64 + f + 1] = cs[nt][1];
            sqm[warp * 64 + f]     = cq[nt][0];
            sqm[warp * 64 + f + 1] = cq[nt][1];
        }
    }
    __syncthreads();
    if (tid < 64) {
        float s = 0.f, qv = 0.f;
#pragma unroll
        for (int w = 0; w < 8; w++) { s += ssm[w * 64 + tid]; qv += sqm[w * 64 + tid]; }
        size_t o = ((size_t)blockIdx.x * B_ + b) * HF_ + h * 64 + tid;
        psum[o] = s;
        pssq[o] = qv;
    }
}

// ---------------- weff ----------------
__global__ __launch_bounds__(256) void weff_kernel(
    const float* __restrict__ W1,
    const float* __restrict__ psum, const float* __restrict__ pssq,
    float* __restrict__ weff)
{
    const int b = blockIdx.y;
    const int c0 = blockIdx.x * 16;
    const int f = threadIdx.x & 63, cr = threadIdx.x >> 6;
#pragma unroll
    for (int i = 0; i < 4; i++) {
        int c = c0 + i * 4 + cr;
        float s = 0.f, qq = 0.f;
#pragma unroll
        for (int zz = 0; zz < 8; zz++) {
            s  += psum[(size_t)(zz * B_ + b) * HF_ + c];
            qq += pssq[(size_t)(zz * B_ + b) * HF_ + c];
        }
        float mean = s * (1.f / (float)S_);
        float var = qq * (1.f / (float)S_) - mean * mean;
        float iv = rsqrtf(var + EPS_);
        float w = W1[c * F_ + f] + ((c & 63) == f ? 1.f : 0.f);
        weff[(size_t)b * HF_ * F_ + (size_t)c * F_ + f] = w * iv;
    }
}

// ---------------- dense1: split-K x2, K-step 32, LDSM A-frags ----------------
__global__ __launch_bounds__(256) void dense1_kernel(
    const float* __restrict__ X, const float* __restrict__ weff,
    float* __restrict__ outp)
{
    extern __shared__ float dsm[];
    const int tid = threadIdx.x;
    const int lane = tid & 31, warp = tid >> 5;
    const int mw = warp & 3;
    const int wn = warp >> 2;
    const int m0 = blockIdx.x * 64;
    const int kbase = blockIdx.y * 512;
    const int b = m0 >> 10;
    const float* Wb = weff + (size_t)b * HF_ * F_;
    float* outh = outp + (size_t)blockIdx.y * (B_ * S_ * F_);

    const uint32_t dsmA = (uint32_t)__cvta_generic_to_shared(dsm);
    const uint32_t mA = (uint32_t)lane >> 3;
    const uint32_t aoff = ((mw * 16 + (mA & 1) * 8 + (lane & 7)) * 36 + (mA >> 1) * 4) * 4;

    float acc[4][4];
#pragma unroll
    for (int i = 0; i < 4; i++)
#pragma unroll
        for (int r = 0; r < 4; r++) acc[i][r] = 0.f;

    auto issue = [&](int k0, int stg) {
        float* As = dsm + stg * 4480;
        float* Ws = As + 2304;
#pragma unroll
        for (int t = 0; t < 2; t++) {
            int idx = tid + t * 256;
            int r = idx >> 3, c4 = idx & 7;
            cpasync16(&As[r * 36 + c4 * 4], &X[(size_t)(m0 + r) * HF_ + k0 + c4 * 4]);
        }
#pragma unroll
        for (int t = 0; t < 2; t++) {
            int idx = tid + t * 256;
            int r = idx >> 4, c4 = idx & 15;
            cpasync16(&Ws[r * 68 + c4 * 4], &Wb[(size_t)(k0 + r) * F_ + c4 * 4]);
        }
        cpasync_commit();
    };

    issue(kbase, 0);
    issue(kbase + 32, 1);
    issue(kbase + 64, 2);

    for (int it = 0; it < 16; it++) {
        cpasync_wait2();
        __syncthreads();
        if (it + 3 < 16) issue(kbase + (it + 3) * 32, (it + 3) & 3);
        else cpasync_commit();

        const uint32_t asA = dsmA + (uint32_t)((it & 3) * 4480) * 4 + aoff;
        const float* Ws = dsm + (it & 3) * 4480 + 2304;
#pragma unroll
        for (int kt = 0; kt < 4; kt++) {
            uint32_t af[4];
            ldsm_x4(af, asA + (uint32_t)(kt * 8) * 4);
            uint32_t bf[4][2];
#pragma unroll
            for (int nt = 0; nt < 4; nt++) {
                int bn = wn * 32 + nt * 8 + (lane >> 2);
                bf[nt][0] = __float_as_uint(Ws[(kt * 8 + (lane & 3)) * 68 + bn]);
                bf[nt][1] = __float_as_uint(Ws[(kt * 8 + (lane & 3) + 4) * 68 + bn]);
            }
#pragma unroll
            for (int nt = 0; nt < 4; nt++)
                mma_tf32(acc[nt], af, bf[nt]);
        }
    }
#pragma unroll
    for (int nt = 0; nt < 4; nt++) {
        int r = m0 + mw * 16 + (lane >> 2);
        int c = wn * 32 + nt * 8 + (lane & 3) * 2;
        *(float2*)&outh[(size_t)r * F_ + c] = make_float2(acc[nt][0], acc[nt][1]);
        *(float2*)&outh[(size_t)(r + 8) * F_ + c] = make_float2(acc[nt][2], acc[nt][3]);
    }
}

// ---------------- final per-channel instance norm (C=64), sums split-K partials ----------------
__global__ __launch_bounds__(1024) void gnorm_final(
    const float* __restrict__ x, float* __restrict__ y)
{
    const int c = blockIdx.x * 32 + threadIdx.x;
    const int b = blockIdx.y;
    const int ty = threadIdx.y;
    const float* x0 = x + (size_t)b * S_ * F_ + c;
    const float* x1 = x0 + (size_t)B_ * S_ * F_;

    float sum = 0.f, ssq = 0.f;
    for (int s = ty; s < S_; s += 32) {
        float v = x0[(size_t)s * F_] + x1[(size_t)s * F_];
        sum += v;
        ssq += v * v;
    }
    __shared__ float rs[32][33], rq[32][33];
    __shared__ float smean[32], sinvs[32];
    rs[ty][threadIdx.x] = sum;
    rq[ty][threadIdx.x] = ssq;
    __syncthreads();
    if (ty == 0) {
        float s = 0.f, qq = 0.f;
#pragma unroll
        for (int i = 0; i < 32; i++) { s += rs[i][threadIdx.x]; qq += rq[i][threadIdx.x]; }
        float mean = s * (1.f / (float)S_);
        float var = qq * (1.f / (float)S_) - mean * mean;
        smean[threadIdx.x] = mean;
        sinvs[threadIdx.x] = rsqrtf(var + EPS_);
    }
    __syncthreads();
    const float mean = smean[threadIdx.x];
    const float inv = sinvs[threadIdx.x];
    float* yb = y + (size_t)b * S_ * F_ + c;
    for (int s = ty; s < S_; s += 32) {
        float v = x0[(size_t)s * F_] + x1[(size_t)s * F_];
        yb[(size_t)s * F_] = (v - mean) * inv;
    }
}

// ---------------- launch ----------------
extern "C" void kernel_launch(void* const* d_in, const int* in_sizes, int n_in,
                              void* d_out, int out_size)
{
    const float* qw = (const float*)d_in[0];
    const float* kw = (const float*)d_in[1];
    const float* vw = (const float*)d_in[2];
    const float* Wq = (const float*)d_in[3];
    const float* bq = (const float*)d_in[4];
    const float* Wk = (const float*)d_in[5];
    const float* bk = (const float*)d_in[6];
    const float* Wv = (const float*)d_in[7];
    const float* bv = (const float*)d_in[8];
    const float* W1 = (const float*)d_in[9];
    float* out = (float*)d_out;

    float *pq, *pk, *pv, *penf, *pout2, *ppsum, *ppssq, *pweff;
    cudaGetSymbolAddress((void**)&pq,    g_q);
    cudaGetSymbolAddress((void**)&pk,    g_k);
    cudaGetSymbolAddress((void**)&pv,    g_v);
    cudaGetSymbolAddress((void**)&penf,  g_enf);
    cudaGetSymbolAddress((void**)&pout2, g_out2);
    cudaGetSymbolAddress((void**)&ppsum, g_psum);
    cudaGetSymbolAddress((void**)&ppssq, g_pssq);
    cudaGetSymbolAddress((void**)&pweff, g_weff);

    static bool attr_done = false;
    if (!attr_done) {
        cudaFuncSetAttribute(qkv_gemm,      cudaFuncAttributeMaxDynamicSharedMemorySize, 75776);
        cudaFuncSetAttribute(attn_tf32,     cudaFuncAttributeMaxDynamicSharedMemorySize, 104448);
        cudaFuncSetAttribute(dense1_kernel, cudaFuncAttributeMaxDynamicSharedMemorySize, 71680);
        attr_done = true;
    }

    qkv_gemm<<<dim3(8, 64, 3), 256, 75776>>>(qw, kw, vw, Wq, Wk, Wv, bq, bk, bv, pq, pk, pv);

    attn_tf32<<<dim3(S_ / 128, H_, B_), 256, 104448>>>(pq, pk, pv, penf, ppsum, ppssq);

    weff_kernel<<<dim3(HF_ / 16, B_), 256>>>(W1, ppsum, ppssq, pweff);

    dense1_kernel<<<dim3((B_ * S_) / 64, 2), 256, 71680>>>(penf, pweff, pout2);

    gnorm_final<<<dim3(F_ / 32, B_), dim3(32, 32)>>>(pout2, out);
}

// round 15
// speedup vs baseline: 1.1734x; 1.0352x over previous
#include <cuda_runtime.h>
#include <cstdint>

#define B_  8
#define S_  1024
#define D_  1024
#define H_  16
#define F_  64
#define HF_ 1024
#define EPS_ 1e-3f

// ---------------- scratch ----------------
__device__ float g_q[B_ * S_ * HF_];
__device__ float g_k[B_ * S_ * HF_];
__device__ float g_v[B_ * S_ * HF_];
__device__ float g_enf[B_ * S_ * HF_];
__device__ float g_out2[2 * B_ * S_ * F_];   // two split-K partials
__device__ float g_psum[8 * B_ * HF_];
__device__ float g_pssq[8 * B_ * HF_];
__device__ float g_weff[B_ * HF_ * F_];

// ---------------- tf32 mma.m16n8k8 ----------------
__device__ __forceinline__ void mma_tf32(float* d, const uint32_t* a, const uint32_t* b) {
    asm volatile(
        "mma.sync.aligned.m16n8k8.row.col.f32.tf32.tf32.f32 "
        "{%0,%1,%2,%3}, {%4,%5,%6,%7}, {%8,%9}, {%0,%1,%2,%3};\n"
        : "+f"(d[0]), "+f"(d[1]), "+f"(d[2]), "+f"(d[3])
        : "r"(a[0]), "r"(a[1]), "r"(a[2]), "r"(a[3]), "r"(b[0]), "r"(b[1]));
}

// ldmatrix x4 on 32-bit data (b16 non-trans trick): reg m of lane t = Mat_m[t/4][t%4] (b32)
__device__ __forceinline__ void ldsm_x4(uint32_t* r, uint32_t addr) {
    asm volatile("ldmatrix.sync.aligned.m8n8.x4.shared.b16 {%0,%1,%2,%3}, [%4];"
        : "=r"(r[0]), "=r"(r[1]), "=r"(r[2]), "=r"(r[3]) : "r"(addr));
}

// ---------------- cp.async helpers ----------------
__device__ __forceinline__ void cpasync16(void* smem, const void* g) {
    uint32_t s = (uint32_t)__cvta_generic_to_shared(smem);
    asm volatile("cp.async.cg.shared.global [%0], [%1], 16;\n" :: "r"(s), "l"(g));
}
__device__ __forceinline__ void cpasync_commit() {
    asm volatile("cp.async.commit_group;\n" ::: "memory");
}
__device__ __forceinline__ void cpasync_wait0() {
    asm volatile("cp.async.wait_group 0;\n" ::: "memory");
}
__device__ __forceinline__ void cpasync_wait2() {
    asm volatile("cp.async.wait_group 2;\n" ::: "memory");
}

// ---------------- merged QKV GEMM, 4-stage ring, LDSM A-frags ----------------
__global__ __launch_bounds__(256) void qkv_gemm(
    const float* __restrict__ A0, const float* __restrict__ A1, const float* __restrict__ A2,
    const float* __restrict__ W0, const float* __restrict__ W1p, const float* __restrict__ W2,
    const float* __restrict__ b0, const float* __restrict__ b1p, const float* __restrict__ b2,
    float* __restrict__ C0, float* __restrict__ C1, float* __restrict__ C2)
{
    extern __shared__ float gsm[];
    const int z = blockIdx.z;
    const float* A    = z == 0 ? A0 : (z == 1 ? A1 : A2);
    const float* W    = z == 0 ? W0 : (z == 1 ? W1p : W2);
    const float* bias = z == 0 ? b0 : (z == 1 ? b1p : b2);
    float*       C    = z == 0 ? C0 : (z == 1 ? C1 : C2);

    const int tid  = threadIdx.x;
    const int lane = tid & 31, warp = tid >> 5;
    const int wm   = warp & 1, wn = warp >> 1;
    const int m0   = blockIdx.y * 128;
    const int n0   = blockIdx.x * 128;

    const uint32_t gsmA = (uint32_t)__cvta_generic_to_shared(gsm);
    const uint32_t mA = (uint32_t)lane >> 3;
    const uint32_t aoff = ((wm * 64 + (mA & 1) * 8 + (lane & 7)) * 20 + (mA >> 1) * 4) * 4;

    float acc[4][4][4];
#pragma unroll
    for (int i = 0; i < 4; i++)
#pragma unroll
        for (int j = 0; j < 4; j++)
#pragma unroll
            for (int r = 0; r < 4; r++) acc[i][j][r] = 0.f;

    auto issue = [&](int k0, int stg) {
        float* As = gsm + stg * 4736;
        float* Ws = As + 2560;
#pragma unroll
        for (int t = 0; t < 2; t++) {
            int idx = tid + t * 256;
            int r = idx >> 2, c4 = idx & 3;
            cpasync16(&As[r * 20 + c4 * 4], &A[(size_t)(m0 + r) * D_ + k0 + c4 * 4]);
        }
#pragma unroll
        for (int t = 0; t < 2; t++) {
            int idx = tid + t * 256;
            int r = idx >> 5, c8 = idx & 31;
            cpasync16(&Ws[r * 136 + c8 * 4], &W[(size_t)(k0 + r) * HF_ + n0 + c8 * 4]);
        }
        cpasync_commit();
    };

    issue(0, 0);
    issue(16, 1);
    issue(32, 2);

    for (int it = 0; it < 64; it++) {
        cpasync_wait2();
        __syncthreads();
        if (it + 3 < 64) issue((it + 3) * 16, (it + 3) & 3);
        else cpasync_commit();

        const uint32_t asA = gsmA + (uint32_t)((it & 3) * 4736) * 4 + aoff;
        const float* Ws = gsm + (it & 3) * 4736 + 2560;
#pragma unroll
        for (int kt = 0; kt < 2; kt++) {
            uint32_t af[4][4];
#pragma unroll
            for (int mt = 0; mt < 4; mt++)
                ldsm_x4(af[mt], asA + (uint32_t)(mt * 320 + kt * 8) * 4);
            uint32_t bf[4][2];
#pragma unroll
            for (int nt = 0; nt < 4; nt++) {
                int bn = wn * 32 + nt * 8 + (lane >> 2);
                bf[nt][0] = __float_as_uint(Ws[(kt * 8 + (lane & 3)) * 136 + bn]);
                bf[nt][1] = __float_as_uint(Ws[(kt * 8 + (lane & 3) + 4) * 136 + bn]);
            }
#pragma unroll
            for (int mt = 0; mt < 4; mt++)
#pragma unroll
                for (int nt = 0; nt < 4; nt++)
                    mma_tf32(acc[mt][nt], af[mt], bf[nt]);
        }
    }

#pragma unroll
    for (int mt = 0; mt < 4; mt++) {
#pragma unroll
        for (int nt = 0; nt < 4; nt++) {
            int r = m0 + wm * 64 + mt * 16 + (lane >> 2);
            int c = n0 + wn * 32 + nt * 8 + (lane & 3) * 2;
            float bv0 = bias[c], bv1 = bias[c + 1];
            *(float2*)&C[(size_t)r * HF_ + c] =
                make_float2(acc[mt][nt][0] + bv0, acc[mt][nt][1] + bv1);
            *(float2*)&C[(size_t)(r + 8) * HF_ + c] =
                make_float2(acc[mt][nt][2] + bv0, acc[mt][nt][3] + bv1);
        }
    }
}

// ---------------- flash attention + fused stats, LDSM frags, MUFU exp ----------------
#define LD 68
__global__ __launch_bounds__(256, 2) void attn_tf32(
    const float* __restrict__ q, const float* __restrict__ k,
    const float* __restrict__ v, float* __restrict__ enf,
    float* __restrict__ psum, float* __restrict__ pssq)
{
    extern __shared__ float sm[];
    float* Ks = sm;                    // [2][64*LD]
    float* Vs = Ks + 2 * 64 * LD;      // [2][64*LD]
    float* Ps = Vs + 2 * 64 * LD;      // [128*LD]

    const int b = blockIdx.z, h = blockIdx.y, i0 = blockIdx.x * 128;
    const int tid = threadIdx.x, lane = tid & 31, warp = tid >> 5;
    const int r0 = warp * 16 + (lane >> 2), r1 = r0 + 8;
    const int lt = lane & 3;

    const uint32_t smb = (uint32_t)__cvta_generic_to_shared(sm);
    const uint32_t KsA = smb;
    const uint32_t PsA = smb + 4u * (4 * 64 * LD);

    const uint32_t jrK = (((uint32_t)lane >> 4) & 1) * 8 + (lane & 7);
    const uint32_t cK  = (((uint32_t)lane >> 3) & 1) * 4;
    const uint32_t koff = (jrK * LD + cK) * 4;
    const uint32_t jrP = warp * 16 + (((uint32_t)lane >> 3) & 1) * 8 + (lane & 7);
    const uint32_t cP  = (((uint32_t)lane >> 4) & 1) * 4;
    const uint32_t paddr0 = PsA + (jrP * LD + cP) * 4;

    auto issue = [&](int c0, int stg) {
        const float* kb = k + (size_t)(b * S_ + c0) * HF_ + h * 64;
        const float* vb = v + (size_t)(b * S_ + c0) * HF_ + h * 64;
        float* Kd = Ks + stg * 64 * LD;
        float* Vd = Vs + stg * 64 * LD;
#pragma unroll
        for (int t = 0; t < 4; t++) {
            int idx = tid + t * 256;
            int r = idx >> 4, c4 = idx & 15;
            cpasync16(&Kd[r * LD + c4 * 4], kb + (size_t)r * HF_ + c4 * 4);
            cpasync16(&Vd[r * LD + c4 * 4], vb + (size_t)r * HF_ + c4 * 4);
        }
        cpasync_commit();
    };

    issue(0, 0);

    for (int idx = tid; idx < 128 * 16; idx += 256) {
        int r = idx >> 4, c4 = idx & 15;
        float4 vq = *(const float4*)&q[(size_t)(b * S_ + i0 + r) * HF_ + h * 64 + c4 * 4];
        vq.x *= 0.125f; vq.y *= 0.125f; vq.z *= 0.125f; vq.w *= 0.125f;
        *(float4*)&Ps[r * LD + c4 * 4] = vq;
    }
    __syncthreads();

    uint32_t qf[8][4];
#pragma unroll
    for (int kt = 0; kt < 8; kt++)
        ldsm_x4(qf[kt], paddr0 + kt * 8 * 4);

    float lrun0 = 0.f, lrun1 = 0.f;
    float oacc[8][4];
#pragma unroll
    for (int i = 0; i < 8; i++)
#pragma unroll
        for (int j = 0; j < 4; j++) oacc[i][j] = 0.f;

    for (int it = 0; it < 16; it++) {
        cpasync_wait0();
        __syncthreads();
        if (it < 15) issue((it + 1) * 64, (it + 1) & 1);

        const uint32_t kbufA = KsA + (it & 1) * (64 * LD * 4) + koff;
        const float* Vc = Vs + (it & 1) * 64 * LD;

        float sacc[8][4];
#pragma unroll
        for (int i = 0; i < 8; i++)
#pragma unroll
            for (int j = 0; j < 4; j++) sacc[i][j] = 0.f;
#pragma unroll
        for (int kt = 0; kt < 8; kt++) {
#pragma unroll
            for (int g = 0; g < 4; g++) {
                uint32_t bm[4];
                ldsm_x4(bm, kbufA + (g * 16 * LD + kt * 8) * 4);
                mma_tf32(sacc[2 * g],     qf[kt], bm);
                mma_tf32(sacc[2 * g + 1], qf[kt], bm + 2);
            }
        }

        // ---- maxless softmax via MUFU.EX2 (idle pipe; cuts FMA-issue pressure) ----
        float sum0 = 0.f, sum1 = 0.f;
#pragma unroll
        for (int nt = 0; nt < 8; nt++) {
            float e0 = __expf(sacc[nt][0]);
            float e1 = __expf(sacc[nt][1]);
            float e2 = __expf(sacc[nt][2]);
            float e3 = __expf(sacc[nt][3]);
            sum0 += e0 + e1; sum1 += e2 + e3;
            int c = nt * 8 + lt * 2;
            *(float2*)&Ps[r0 * LD + c] = make_float2(e0, e1);
            *(float2*)&Ps[r1 * LD + c] = make_float2(e2, e3);
        }
        sum0 += __shfl_xor_sync(0xffffffffu, sum0, 1);
        sum0 += __shfl_xor_sync(0xffffffffu, sum0, 2);
        sum1 += __shfl_xor_sync(0xffffffffu, sum1, 1);
        sum1 += __shfl_xor_sync(0xffffffffu, sum1, 2);
        lrun0 += sum0;
        lrun1 += sum1;
        __syncwarp();

#pragma unroll
        for (int kt = 0; kt < 8; kt++) {
            uint32_t af[4];
            ldsm_x4(af, paddr0 + kt * 8 * 4);
#pragma unroll
            for (int nt = 0; nt < 8; nt++) {
                uint32_t bf[2];
                int fn = nt * 8 + (lane >> 2);
                bf[0] = __float_as_uint(Vc[(kt * 8 + lt) * LD + fn]);
                bf[1] = __float_as_uint(Vc[(kt * 8 + lt + 4) * LD + fn]);
                mma_tf32(oacc[nt], af, bf);
            }
        }
    }

    float cs[8][2], cq[8][2];
    {
        float li0 = 1.f / lrun0, li1 = 1.f / lrun1;
#pragma unroll
        for (int nt = 0; nt < 8; nt++) {
            int c = nt * 8 + lt * 2;
            size_t a0 = (size_t)(b * S_ + i0 + r0) * HF_ + h * 64 + c;
            size_t a1 = (size_t)(b * S_ + i0 + r1) * HF_ + h * 64 + c;
            float2 q0 = *(const float2*)&q[a0];
            float2 q1 = *(const float2*)&q[a1];
            float2 o0 = make_float2(oacc[nt][0] * li0 + q0.x, oacc[nt][1] * li0 + q0.y);
            float2 o1 = make_float2(oacc[nt][2] * li1 + q1.x, oacc[nt][3] * li1 + q1.y);
            *(float2*)&enf[a0] = o0;
            *(float2*)&enf[a1] = o1;
            cs[nt][0] = o0.x + o1.x;            cs[nt][1] = o0.y + o1.y;
            cq[nt][0] = o0.x * o0.x + o1.x * o1.x;
            cq[nt][1] = o0.y * o0.y + o1.y * o1.y;
        }
    }
#pragma unroll
    for (int nt = 0; nt < 8; nt++)
#pragma unroll
        for (int j = 0; j < 2; j++) {
            cs[nt][j] += __shfl_xor_sync(0xffffffffu, cs[nt][j], 4);
            cs[nt][j] += __shfl_xor_sync(0xffffffffu, cs[nt][j], 8);
            cs[nt][j] += __shfl_xor_sync(0xffffffffu, cs[nt][j], 16);
            cq[nt][j] += __shfl_xor_sync(0xffffffffu, cq[nt][j], 4);
            cq[nt][j] += __shfl_xor_sync(0xffffffffu, cq[nt][j], 8);
            cq[nt][j] += __shfl_xor_sync(0xffffffffu, cq[nt][j], 16);
        }
    __syncthreads();
    float* ssm = Ps;
    float* sqm = Ps + 512;
    if (lane < 4) {
#pragma unroll
        for (int nt = 0; nt < 8; nt++) {
            int f = nt * 8 + lane * 2;
            ssm[warp * 64 + f]     = cs[nt][0];
            ssm[warp * 64 + f + 1] = cs[nt][1];
            sqm[warp * 64 + f]     = cq[nt][0];
            sqm[warp * 64 + f + 1] = cq[nt][1];
        }
    }
    __syncthreads();
    if (tid < 64) {
        float s = 0.f, qv = 0.f;
#pragma unroll
        for (int w = 0; w < 8; w++) { s += ssm[w * 64 + tid]; qv += sqm[w * 64 + tid]; }
        size_t o = ((size_t)blockIdx.x * B_ + b) * HF_ + h * 64 + tid;
        psum[o] = s;
        pssq[o] = qv;
    }
}

// ---------------- weff ----------------
__global__ __launch_bounds__(256) void weff_kernel(
    const float* __restrict__ W1,
    const float* __restrict__ psum, const float* __restrict__ pssq,
    float* __restrict__ weff)
{
    const int b = blockIdx.y;
    const int c0 = blockIdx.x * 16;
    const int f = threadIdx.x & 63, cr = threadIdx.x >> 6;
#pragma unroll
    for (int i = 0; i < 4; i++) {
        int c = c0 + i * 4 + cr;
        float s = 0.f, qq = 0.f;
#pragma unroll
        for (int zz = 0; zz < 8; zz++) {
            s  += psum[(size_t)(zz * B_ + b) * HF_ + c];
            qq += pssq[(size_t)(zz * B_ + b) * HF_ + c];
        }
        float mean = s * (1.f / (float)S_);
        float var = qq * (1.f / (float)S_) - mean * mean;
        float iv = rsqrtf(var + EPS_);
        float w = W1[c * F_ + f] + ((c & 63) == f ? 1.f : 0.f);
        weff[(size_t)b * HF_ * F_ + (size_t)c * F_ + f] = w * iv;
    }
}

// ---------------- dense1: split-K x2, K-step 32, LDSM A-frags ----------------
__global__ __launch_bounds__(256) void dense1_kernel(
    const float* __restrict__ X, const float* __restrict__ weff,
    float* __restrict__ outp)
{
    extern __shared__ float dsm[];
    const int tid = threadIdx.x;
    const int lane = tid & 31, warp = tid >> 5;
    const int mw = warp & 3;
    const int wn = warp >> 2;
    const int m0 = blockIdx.x * 64;
    const int kbase = blockIdx.y * 512;
    const int b = m0 >> 10;
    const float* Wb = weff + (size_t)b * HF_ * F_;
    float* outh = outp + (size_t)blockIdx.y * (B_ * S_ * F_);

    const uint32_t dsmA = (uint32_t)__cvta_generic_to_shared(dsm);
    const uint32_t mA = (uint32_t)lane >> 3;
    const uint32_t aoff = ((mw * 16 + (mA & 1) * 8 + (lane & 7)) * 36 + (mA >> 1) * 4) * 4;

    float acc[4][4];
#pragma unroll
    for (int i = 0; i < 4; i++)
#pragma unroll
        for (int r = 0; r < 4; r++) acc[i][r] = 0.f;

    auto issue = [&](int k0, int stg) {
        float* As = dsm + stg * 4480;
        float* Ws = As + 2304;
#pragma unroll
        for (int t = 0; t < 2; t++) {
            int idx = tid + t * 256;
            int r = idx >> 3, c4 = idx & 7;
            cpasync16(&As[r * 36 + c4 * 4], &X[(size_t)(m0 + r) * HF_ + k0 + c4 * 4]);
        }
#pragma unroll
        for (int t = 0; t < 2; t++) {
            int idx = tid + t * 256;
            int r = idx >> 4, c4 = idx & 15;
            cpasync16(&Ws[r * 68 + c4 * 4], &Wb[(size_t)(k0 + r) * F_ + c4 * 4]);
        }
        cpasync_commit();
    };

    issue(kbase, 0);
    issue(kbase + 32, 1);
    issue(kbase + 64, 2);

    for (int it = 0; it < 16; it++) {
        cpasync_wait2();
        __syncthreads();
        if (it + 3 < 16) issue(kbase + (it + 3) * 32, (it + 3) & 3);
        else cpasync_commit();

        const uint32_t asA = dsmA + (uint32_t)((it & 3) * 4480) * 4 + aoff;
        const float* Ws = dsm + (it & 3) * 4480 + 2304;
#pragma unroll
        for (int kt = 0; kt < 4; kt++) {
            uint32_t af[4];
            ldsm_x4(af, asA + (uint32_t)(kt * 8) * 4);
            uint32_t bf[4][2];
#pragma unroll
            for (int nt = 0; nt < 4; nt++) {
                int bn = wn * 32 + nt * 8 + (lane >> 2);
                bf[nt][0] = __float_as_uint(Ws[(kt * 8 + (lane & 3)) * 68 + bn]);
                bf[nt][1] = __float_as_uint(Ws[(kt * 8 + (lane & 3) + 4) * 68 + bn]);
            }
#pragma unroll
            for (int nt = 0; nt < 4; nt++)
                mma_tf32(acc[nt], af, bf[nt]);
        }
    }
#pragma unroll
    for (int nt = 0; nt < 4; nt++) {
        int r = m0 + mw * 16 + (lane >> 2);
        int c = wn * 32 + nt * 8 + (lane & 3) * 2;
        *(float2*)&outh[(size_t)r * F_ + c] = make_float2(acc[nt][0], acc[nt][1]);
        *(float2*)&outh[(size_t)(r + 8) * F_ + c] = make_float2(acc[nt][2], acc[nt][3]);
    }
}

// ---------------- final per-channel instance norm (C=64), sums split-K partials ----------------
__global__ __launch_bounds__(1024) void gnorm_final(
    const float* __restrict__ x, float* __restrict__ y)
{
    const int c = blockIdx.x * 32 + threadIdx.x;
    const int b = blockIdx.y;
    const int ty = threadIdx.y;
    const float* x0 = x + (size_t)b * S_ * F_ + c;
    const float* x1 = x0 + (size_t)B_ * S_ * F_;

    float sum = 0.f, ssq = 0.f;
    for (int s = ty; s < S_; s += 32) {
        float v = x0[(size_t)s * F_] + x1[(size_t)s * F_];
        sum += v;
        ssq += v * v;
    }
    __shared__ float rs[32][33], rq[32][33];
    __shared__ float smean[32], sinvs[32];
    rs[ty][threadIdx.x] = sum;
    rq[ty][threadIdx.x] = ssq;
    __syncthreads();
    if (ty == 0) {
        float s = 0.f, qq = 0.f;
#pragma unroll
        for (int i = 0; i < 32; i++) { s += rs[i][threadIdx.x]; qq += rq[i][threadIdx.x]; }
        float mean = s * (1.f / (float)S_);
        float var = qq * (1.f / (float)S_) - mean * mean;
        smean[threadIdx.x] = mean;
        sinvs[threadIdx.x] = rsqrtf(var + EPS_);
    }
    __syncthreads();
    const float mean = smean[threadIdx.x];
    const float inv = sinvs[threadIdx.x];
    float* yb = y + (size_t)b * S_ * F_ + c;
    for (int s = ty; s < S_; s += 32) {
        float v = x0[(size_t)s * F_] + x1[(size_t)s * F_];
        yb[(size_t)s * F_] = (v - mean) * inv;
    }
}

// ---------------- launch ----------------
extern "C" void kernel_launch(void* const* d_in, const int* in_sizes, int n_in,
                              void* d_out, int out_size)
{
    const float* qw = (const float*)d_in[0];
    const float* kw = (const float*)d_in[1];
    const float* vw = (const float*)d_in[2];
    const float* Wq = (const float*)d_in[3];
    const float* bq = (const float*)d_in[4];
    const float* Wk = (const float*)d_in[5];
    const float* bk = (const float*)d_in[6];
    const float* Wv = (const float*)d_in[7];
    const float* bv = (const float*)d_in[8];
    const float* W1 = (const float*)d_in[9];
    float* out = (float*)d_out;

    float *pq, *pk, *pv, *penf, *pout2, *ppsum, *ppssq, *pweff;
    cudaGetSymbolAddress((void**)&pq,    g_q);
    cudaGetSymbolAddress((void**)&pk,    g_k);
    cudaGetSymbolAddress((void**)&pv,    g_v);
    cudaGetSymbolAddress((void**)&penf,  g_enf);
    cudaGetSymbolAddress((void**)&pout2, g_out2);
    cudaGetSymbolAddress((void**)&ppsum, g_psum);
    cudaGetSymbolAddress((void**)&ppssq, g_pssq);
    cudaGetSymbolAddress((void**)&pweff, g_weff);

    static bool attr_done = false;
    if (!attr_done) {
        cudaFuncSetAttribute(qkv_gemm,      cudaFuncAttributeMaxDynamicSharedMemorySize, 75776);
        cudaFuncSetAttribute(attn_tf32,     cudaFuncAttributeMaxDynamicSharedMemorySize, 104448);
        cudaFuncSetAttribute(dense1_kernel, cudaFuncAttributeMaxDynamicSharedMemorySize, 71680);
        attr_done = true;
    }

    qkv_gemm<<<dim3(8, 64, 3), 256, 75776>>>(qw, kw, vw, Wq, Wk, Wv, bq, bk, bv, pq, pk, pv);

    attn_tf32<<<dim3(S_ / 128, H_, B_), 256, 104448>>>(pq, pk, pv, penf, ppsum, ppssq);

    weff_kernel<<<dim3(HF_ / 16, B_), 256>>>(W1, ppsum, ppssq, pweff);

    dense1_kernel<<<dim3((B_ * S_) / 64, 2), 256, 71680>>>(penf, pweff, pout2);

    gnorm_final<<<dim3(F_ / 32, B_), dim3(32, 32)>>>(pout2, out);
}

// round 16
// speedup vs baseline: 1.2729x; 1.0848x over previous
#include <cuda_runtime.h>
#include <cstdint>

#define B_  8
#define S_  1024
#define D_  1024
#define H_  16
#define F_  64
#define HF_ 1024
#define EPS_ 1e-3f

// ---------------- scratch ----------------
__device__ float g_q[B_ * S_ * HF_];
__device__ float g_k[B_ * S_ * HF_];
__device__ float g_vt[B_ * HF_ * S_];        // V transposed: [b][hf][s]
__device__ float g_enf[B_ * S_ * HF_];
__device__ float g_out2[2 * B_ * S_ * F_];   // two split-K partials
__device__ float g_psum[8 * B_ * HF_];
__device__ float g_pssq[8 * B_ * HF_];
__device__ float g_weff[B_ * HF_ * F_];

// ---------------- tf32 mma.m16n8k8 ----------------
__device__ __forceinline__ void mma_tf32(float* d, const uint32_t* a, const uint32_t* b) {
    asm volatile(
        "mma.sync.aligned.m16n8k8.row.col.f32.tf32.tf32.f32 "
        "{%0,%1,%2,%3}, {%4,%5,%6,%7}, {%8,%9}, {%0,%1,%2,%3};\n"
        : "+f"(d[0]), "+f"(d[1]), "+f"(d[2]), "+f"(d[3])
        : "r"(a[0]), "r"(a[1]), "r"(a[2]), "r"(a[3]), "r"(b[0]), "r"(b[1]));
}

// ldmatrix x4 on 32-bit data (b16 non-trans trick): reg m of lane t = Mat_m[t/4][t%4] (b32)
__device__ __forceinline__ void ldsm_x4(uint32_t* r, uint32_t addr) {
    asm volatile("ldmatrix.sync.aligned.m8n8.x4.shared.b16 {%0,%1,%2,%3}, [%4];"
        : "=r"(r[0]), "=r"(r[1]), "=r"(r[2]), "=r"(r[3]) : "r"(addr));
}

// ---------------- cp.async helpers ----------------
__device__ __forceinline__ void cpasync16(void* smem, const void* g) {
    uint32_t s = (uint32_t)__cvta_generic_to_shared(smem);
    asm volatile("cp.async.cg.shared.global [%0], [%1], 16;\n" :: "r"(s), "l"(g));
}
__device__ __forceinline__ void cpasync_commit() {
    asm volatile("cp.async.commit_group;\n" ::: "memory");
}
__device__ __forceinline__ void cpasync_wait0() {
    asm volatile("cp.async.wait_group 0;\n" ::: "memory");
}
__device__ __forceinline__ void cpasync_wait2() {
    asm volatile("cp.async.wait_group 2;\n" ::: "memory");
}

// ---------------- merged QKV GEMM, 4-stage ring, LDSM A-frags ----------------
// z==2 (V) writes transposed: vt[b][hf][s].
__global__ __launch_bounds__(256) void qkv_gemm(
    const float* __restrict__ A0, const float* __restrict__ A1, const float* __restrict__ A2,
    const float* __restrict__ W0, const float* __restrict__ W1p, const float* __restrict__ W2,
    const float* __restrict__ b0, const float* __restrict__ b1p, const float* __restrict__ b2,
    float* __restrict__ C0, float* __restrict__ C1, float* __restrict__ C2)
{
    extern __shared__ float gsm[];
    const int z = blockIdx.z;
    const float* A    = z == 0 ? A0 : (z == 1 ? A1 : A2);
    const float* W    = z == 0 ? W0 : (z == 1 ? W1p : W2);
    const float* bias = z == 0 ? b0 : (z == 1 ? b1p : b2);
    float*       C    = z == 0 ? C0 : (z == 1 ? C1 : C2);

    const int tid  = threadIdx.x;
    const int lane = tid & 31, warp = tid >> 5;
    const int wm   = warp & 1, wn = warp >> 1;
    const int m0   = blockIdx.y * 128;
    const int n0   = blockIdx.x * 128;

    const uint32_t gsmA = (uint32_t)__cvta_generic_to_shared(gsm);
    const uint32_t mA = (uint32_t)lane >> 3;
    const uint32_t aoff = ((wm * 64 + (mA & 1) * 8 + (lane & 7)) * 20 + (mA >> 1) * 4) * 4;

    float acc[4][4][4];
#pragma unroll
    for (int i = 0; i < 4; i++)
#pragma unroll
        for (int j = 0; j < 4; j++)
#pragma unroll
            for (int r = 0; r < 4; r++) acc[i][j][r] = 0.f;

    auto issue = [&](int k0, int stg) {
        float* As = gsm + stg * 4736;
        float* Ws = As + 2560;
#pragma unroll
        for (int t = 0; t < 2; t++) {
            int idx = tid + t * 256;
            int r = idx >> 2, c4 = idx & 3;
            cpasync16(&As[r * 20 + c4 * 4], &A[(size_t)(m0 + r) * D_ + k0 + c4 * 4]);
        }
#pragma unroll
        for (int t = 0; t < 2; t++) {
            int idx = tid + t * 256;
            int r = idx >> 5, c8 = idx & 31;
            cpasync16(&Ws[r * 136 + c8 * 4], &W[(size_t)(k0 + r) * HF_ + n0 + c8 * 4]);
        }
        cpasync_commit();
    };

    issue(0, 0);
    issue(16, 1);
    issue(32, 2);

    for (int it = 0; it < 64; it++) {
        cpasync_wait2();
        __syncthreads();
        if (it + 3 < 64) issue((it + 3) * 16, (it + 3) & 3);
        else cpasync_commit();

        const uint32_t asA = gsmA + (uint32_t)((it & 3) * 4736) * 4 + aoff;
        const float* Ws = gsm + (it & 3) * 4736 + 2560;
#pragma unroll
        for (int kt = 0; kt < 2; kt++) {
            uint32_t af[4][4];
#pragma unroll
            for (int mt = 0; mt < 4; mt++)
                ldsm_x4(af[mt], asA + (uint32_t)(mt * 320 + kt * 8) * 4);
            uint32_t bf[4][2];
#pragma unroll
            for (int nt = 0; nt < 4; nt++) {
                int bn = wn * 32 + nt * 8 + (lane >> 2);
                bf[nt][0] = __float_as_uint(Ws[(kt * 8 + (lane & 3)) * 136 + bn]);
                bf[nt][1] = __float_as_uint(Ws[(kt * 8 + (lane & 3) + 4) * 136 + bn]);
            }
#pragma unroll
            for (int mt = 0; mt < 4; mt++)
#pragma unroll
                for (int nt = 0; nt < 4; nt++)
                    mma_tf32(acc[mt][nt], af[mt], bf[nt]);
        }
    }

    const int bb = m0 >> 10;
#pragma unroll
    for (int mt = 0; mt < 4; mt++) {
#pragma unroll
        for (int nt = 0; nt < 4; nt++) {
            int r = m0 + wm * 64 + mt * 16 + (lane >> 2);
            int c = n0 + wn * 32 + nt * 8 + (lane & 3) * 2;
            float bv0 = bias[c], bv1 = bias[c + 1];
            if (z == 2) {
                int s = r & 1023;
                size_t base0 = ((size_t)bb * HF_ + c) * S_;
                size_t base1 = ((size_t)bb * HF_ + c + 1) * S_;
                C[base0 + s]     = acc[mt][nt][0] + bv0;
                C[base1 + s]     = acc[mt][nt][1] + bv1;
                C[base0 + s + 8] = acc[mt][nt][2] + bv0;
                C[base1 + s + 8] = acc[mt][nt][3] + bv1;
            } else {
                *(float2*)&C[(size_t)r * HF_ + c] =
                    make_float2(acc[mt][nt][0] + bv0, acc[mt][nt][1] + bv1);
                *(float2*)&C[(size_t)(r + 8) * HF_ + c] =
                    make_float2(acc[mt][nt][2] + bv0, acc[mt][nt][3] + bv1);
            }
        }
    }
}

// ---------------- flash attention + fused stats, full-LDSM fragment loads ----------------
#define LD 68
__global__ __launch_bounds__(256, 2) void attn_tf32(
    const float* __restrict__ q, const float* __restrict__ k,
    const float* __restrict__ vt, float* __restrict__ enf,
    float* __restrict__ psum, float* __restrict__ pssq)
{
    extern __shared__ float sm[];
    float* Ks = sm;                    // [2][64*LD]  rows j, cols k
    float* Vs = Ks + 2 * 64 * LD;      // [2][64*LD]  rows f, cols j (from vt)
    float* Ps = Vs + 2 * 64 * LD;      // [128*LD]

    const int b = blockIdx.z, h = blockIdx.y, i0 = blockIdx.x * 128;
    const int tid = threadIdx.x, lane = tid & 31, warp = tid >> 5;
    const int r0 = warp * 16 + (lane >> 2), r1 = r0 + 8;
    const int lt = lane & 3;

    const uint32_t smb = (uint32_t)__cvta_generic_to_shared(sm);
    const uint32_t KsA = smb;
    const uint32_t VsA = smb + 4u * (2 * 64 * LD);
    const uint32_t PsA = smb + 4u * (4 * 64 * LD);

    // shared LDSM thread-offset pattern for K and V (B-operand, 4-mat groups)
    const uint32_t jrB = (((uint32_t)lane >> 4) & 1) * 8 + (lane & 7);
    const uint32_t cB  = (((uint32_t)lane >> 3) & 1) * 4;
    const uint32_t boff = (jrB * LD + cB) * 4;
    const uint32_t jrP = warp * 16 + (((uint32_t)lane >> 3) & 1) * 8 + (lane & 7);
    const uint32_t cP  = (((uint32_t)lane >> 4) & 1) * 4;
    const uint32_t paddr0 = PsA + (jrP * LD + cP) * 4;

    auto issue = [&](int c0, int stg) {
        const float* kb = k + (size_t)(b * S_ + c0) * HF_ + h * 64;
        const float* vb = vt + ((size_t)b * HF_ + h * 64) * S_ + c0;
        float* Kd = Ks + stg * 64 * LD;
        float* Vd = Vs + stg * 64 * LD;
#pragma unroll
        for (int t = 0; t < 4; t++) {
            int idx = tid + t * 256;
            int r = idx >> 4, c4 = idx & 15;
            cpasync16(&Kd[r * LD + c4 * 4], kb + (size_t)r * HF_ + c4 * 4);
            cpasync16(&Vd[r * LD + c4 * 4], vb + (size_t)r * S_ + c4 * 4);
        }
        cpasync_commit();
    };

    issue(0, 0);

    for (int idx = tid; idx < 128 * 16; idx += 256) {
        int r = idx >> 4, c4 = idx & 15;
        float4 vq = *(const float4*)&q[(size_t)(b * S_ + i0 + r) * HF_ + h * 64 + c4 * 4];
        vq.x *= 0.125f; vq.y *= 0.125f; vq.z *= 0.125f; vq.w *= 0.125f;
        *(float4*)&Ps[r * LD + c4 * 4] = vq;
    }
    __syncthreads();

    uint32_t qf[8][4];
#pragma unroll
    for (int kt = 0; kt < 8; kt++)
        ldsm_x4(qf[kt], paddr0 + kt * 8 * 4);

    float lrun0 = 0.f, lrun1 = 0.f;
    float oacc[8][4];
#pragma unroll
    for (int i = 0; i < 8; i++)
#pragma unroll
        for (int j = 0; j < 4; j++) oacc[i][j] = 0.f;

    for (int it = 0; it < 16; it++) {
        cpasync_wait0();
        __syncthreads();
        if (it < 15) issue((it + 1) * 64, (it + 1) & 1);

        const uint32_t kbufA = KsA + (it & 1) * (64 * LD * 4) + boff;
        const uint32_t vbufA = VsA + (it & 1) * (64 * LD * 4) + boff;

        float sacc[8][4];
#pragma unroll
        for (int i = 0; i < 8; i++)
#pragma unroll
            for (int j = 0; j < 4; j++) sacc[i][j] = 0.f;
#pragma unroll
        for (int kt = 0; kt < 8; kt++) {
#pragma unroll
            for (int g = 0; g < 4; g++) {
                uint32_t bm[4];
                ldsm_x4(bm, kbufA + (g * 16 * LD + kt * 8) * 4);
                mma_tf32(sacc[2 * g],     qf[kt], bm);
                mma_tf32(sacc[2 * g + 1], qf[kt], bm + 2);
            }
        }

        // ---- maxless softmax via MUFU.EX2 ----
        float sum0 = 0.f, sum1 = 0.f;
#pragma unroll
        for (int nt = 0; nt < 8; nt++) {
            float e0 = __expf(sacc[nt][0]);
            float e1 = __expf(sacc[nt][1]);
            float e2 = __expf(sacc[nt][2]);
            float e3 = __expf(sacc[nt][3]);
            sum0 += e0 + e1; sum1 += e2 + e3;
            int c = nt * 8 + lt * 2;
            *(float2*)&Ps[r0 * LD + c] = make_float2(e0, e1);
            *(float2*)&Ps[r1 * LD + c] = make_float2(e2, e3);
        }
        sum0 += __shfl_xor_sync(0xffffffffu, sum0, 1);
        sum0 += __shfl_xor_sync(0xffffffffu, sum0, 2);
        sum1 += __shfl_xor_sync(0xffffffffu, sum1, 1);
        sum1 += __shfl_xor_sync(0xffffffffu, sum1, 2);
        lrun0 += sum0;
        lrun1 += sum1;
        __syncwarp();

        // ---- O += P @ V : both operands via LDSM ----
#pragma unroll
        for (int kt = 0; kt < 8; kt++) {
            uint32_t af[4];
            ldsm_x4(af, paddr0 + kt * 8 * 4);
#pragma unroll
            for (int g = 0; g < 4; g++) {
                uint32_t bm[4];
                ldsm_x4(bm, vbufA + (g * 16 * LD + kt * 8) * 4);
                mma_tf32(oacc[2 * g],     af, bm);
                mma_tf32(oacc[2 * g + 1], af, bm + 2);
            }
        }
    }

    float cs[8][2], cq[8][2];
    {
        float li0 = 1.f / lrun0, li1 = 1.f / lrun1;
#pragma unroll
        for (int nt = 0; nt < 8; nt++) {
            int c = nt * 8 + lt * 2;
            size_t a0 = (size_t)(b * S_ + i0 + r0) * HF_ + h * 64 + c;
            size_t a1 = (size_t)(b * S_ + i0 + r1) * HF_ + h * 64 + c;
            float2 q0 = *(const float2*)&q[a0];
            float2 q1 = *(const float2*)&q[a1];
            float2 o0 = make_float2(oacc[nt][0] * li0 + q0.x, oacc[nt][1] * li0 + q0.y);
            float2 o1 = make_float2(oacc[nt][2] * li1 + q1.x, oacc[nt][3] * li1 + q1.y);
            *(float2*)&enf[a0] = o0;
            *(float2*)&enf[a1] = o1;
            cs[nt][0] = o0.x + o1.x;            cs[nt][1] = o0.y + o1.y;
            cq[nt][0] = o0.x * o0.x + o1.x * o1.x;
            cq[nt][1] = o0.y * o0.y + o1.y * o1.y;
        }
    }
#pragma unroll
    for (int nt = 0; nt < 8; nt++)
#pragma unroll
        for (int j = 0; j < 2; j++) {
            cs[nt][j] += __shfl_xor_sync(0xffffffffu, cs[nt][j], 4);
            cs[nt][j] += __shfl_xor_sync(0xffffffffu, cs[nt][j], 8);
            cs[nt][j] += __shfl_xor_sync(0xffffffffu, cs[nt][j], 16);
            cq[nt][j] += __shfl_xor_sync(0xffffffffu, cq[nt][j], 4);
            cq[nt][j] += __shfl_xor_sync(0xffffffffu, cq[nt][j], 8);
            cq[nt][j] += __shfl_xor_sync(0xffffffffu, cq[nt][j], 16);
        }
    __syncthreads();
    float* ssm = Ps;
    float* sqm = Ps + 512;
    if (lane < 4) {
#pragma unroll
        for (int nt = 0; nt < 8; nt++) {
            int f = nt * 8 + lane * 2;
            ssm[warp * 64 + f]     = cs[nt][0];
            ssm[warp * 64 + f + 1] = cs[nt][1];
            sqm[warp * 64 + f]     = cq[nt][0];
            sqm[warp * 64 + f + 1] = cq[nt][1];
        }
    }
    __syncthreads();
    if (tid < 64) {
        float s = 0.f, qv = 0.f;
#pragma unroll
        for (int w = 0; w < 8; w++) { s += ssm[w * 64 + tid]; qv += sqm[w * 64 + tid]; }
        size_t o = ((size_t)blockIdx.x * B_ + b) * HF_ + h * 64 + tid;
        psum[o] = s;
        pssq[o] = qv;
    }
}

// ---------------- weff ----------------
__global__ __launch_bounds__(256) void weff_kernel(
    const float* __restrict__ W1,
    const float* __restrict__ psum, const float* __restrict__ pssq,
    float* __restrict__ weff)
{
    const int b = blockIdx.y;
    const int c0 = blockIdx.x * 16;
    const int f = threadIdx.x & 63, cr = threadIdx.x >> 6;
#pragma unroll
    for (int i = 0; i < 4; i++) {
        int c = c0 + i * 4 + cr;
        float s = 0.f, qq = 0.f;
#pragma unroll
        for (int zz = 0; zz < 8; zz++) {
            s  += psum[(size_t)(zz * B_ + b) * HF_ + c];
            qq += pssq[(size_t)(zz * B_ + b) * HF_ + c];
        }
        float mean = s * (1.f / (float)S_);
        float var = qq * (1.f / (float)S_) - mean * mean;
        float iv = rsqrtf(var + EPS_);
        float w = W1[c * F_ + f] + ((c & 63) == f ? 1.f : 0.f);
        weff[(size_t)b * HF_ * F_ + (size_t)c * F_ + f] = w * iv;
    }
}

// ---------------- dense1: split-K x2, K-step 32, LDSM A-frags ----------------
__global__ __launch_bounds__(256) void dense1_kernel(
    const float* __restrict__ X, const float* __restrict__ weff,
    float* __restrict__ outp)
{
    extern __shared__ float dsm[];
    const int tid = threadIdx.x;
    const int lane = tid & 31, warp = tid >> 5;
    const int mw = warp & 3;
    const int wn = warp >> 2;
    const int m0 = blockIdx.x * 64;
    const int kbase = blockIdx.y * 512;
    const int b = m0 >> 10;
    const float* Wb = weff + (size_t)b * HF_ * F_;
    float* outh = outp + (size_t)blockIdx.y * (B_ * S_ * F_);

    const uint32_t dsmA = (uint32_t)__cvta_generic_to_shared(dsm);
    const uint32_t mA = (uint32_t)lane >> 3;
    const uint32_t aoff = ((mw * 16 + (mA & 1) * 8 + (lane & 7)) * 36 + (mA >> 1) * 4) * 4;

    float acc[4][4];
#pragma unroll
    for (int i = 0; i < 4; i++)
#pragma unroll
        for (int r = 0; r < 4; r++) acc[i][r] = 0.f;

    auto issue = [&](int k0, int stg) {
        float* As = dsm + stg * 4480;
        float* Ws = As + 2304;
#pragma unroll
        for (int t = 0; t < 2; t++) {
            int idx = tid + t * 256;
            int r = idx >> 3, c4 = idx & 7;
            cpasync16(&As[r * 36 + c4 * 4], &X[(size_t)(m0 + r) * HF_ + k0 + c4 * 4]);
        }
#pragma unroll
        for (int t = 0; t < 2; t++) {
            int idx = tid + t * 256;
            int r = idx >> 4, c4 = idx & 15;
            cpasync16(&Ws[r * 68 + c4 * 4], &Wb[(size_t)(k0 + r) * F_ + c4 * 4]);
        }
        cpasync_commit();
    };

    issue(kbase, 0);
    issue(kbase + 32, 1);
    issue(kbase + 64, 2);

    for (int it = 0; it < 16; it++) {
        cpasync_wait2();
        __syncthreads();
        if (it + 3 < 16) issue(kbase + (it + 3) * 32, (it + 3) & 3);
        else cpasync_commit();

        const uint32_t asA = dsmA + (uint32_t)((it & 3) * 4480) * 4 + aoff;
        const float* Ws = dsm + (it & 3) * 4480 + 2304;
#pragma unroll
        for (int kt = 0; kt < 4; kt++) {
            uint32_t af[4];
            ldsm_x4(af, asA + (uint32_t)(kt * 8) * 4);
            uint32_t bf[4][2];
#pragma unroll
            for (int nt = 0; nt < 4; nt++) {
                int bn = wn * 32 + nt * 8 + (lane >> 2);
                bf[nt][0] = __float_as_uint(Ws[(kt * 8 + (lane & 3)) * 68 + bn]);
                bf[nt][1] = __float_as_uint(Ws[(kt * 8 + (lane & 3) + 4) * 68 + bn]);
            }
#pragma unroll
            for (int nt = 0; nt < 4; nt++)
                mma_tf32(acc[nt], af, bf[nt]);
        }
    }
#pragma unroll
    for (int nt = 0; nt < 4; nt++) {
        int r = m0 + mw * 16 + (lane >> 2);
        int c = wn * 32 + nt * 8 + (lane & 3) * 2;
        *(float2*)&outh[(size_t)r * F_ + c] = make_float2(acc[nt][0], acc[nt][1]);
        *(float2*)&outh[(size_t)(r + 8) * F_ + c] = make_float2(acc[nt][2], acc[nt][3]);
    }
}

// ---------------- final per-channel instance norm (C=64), sums split-K partials ----------------
__global__ __launch_bounds__(1024) void gnorm_final(
    const float* __restrict__ x, float* __restrict__ y)
{
    const int c = blockIdx.x * 32 + threadIdx.x;
    const int b = blockIdx.y;
    const int ty = threadIdx.y;
    const float* x0 = x + (size_t)b * S_ * F_ + c;
    const float* x1 = x0 + (size_t)B_ * S_ * F_;

    float sum = 0.f, ssq = 0.f;
    for (int s = ty; s < S_; s += 32) {
        float v = x0[(size_t)s * F_] + x1[(size_t)s * F_];
        sum += v;
        ssq += v * v;
    }
    __shared__ float rs[32][33], rq[32][33];
    __shared__ float smean[32], sinvs[32];
    rs[ty][threadIdx.x] = sum;
    rq[ty][threadIdx.x] = ssq;
    __syncthreads();
    if (ty == 0) {
        float s = 0.f, qq = 0.f;
#pragma unroll
        for (int i = 0; i < 32; i++) { s += rs[i][threadIdx.x]; qq += rq[i][threadIdx.x]; }
        float mean = s * (1.f / (float)S_);
        float var = qq * (1.f / (float)S_) - mean * mean;
        smean[threadIdx.x] = mean;
        sinvs[threadIdx.x] = rsqrtf(var + EPS_);
    }
    __syncthreads();
    const float mean = smean[threadIdx.x];
    const float inv = sinvs[threadIdx.x];
    float* yb = y + (size_t)b * S_ * F_ + c;
    for (int s = ty; s < S_; s += 32) {
        float v = x0[(size_t)s * F_] + x1[(size_t)s * F_];
        yb[(size_t)s * F_] = (v - mean) * inv;
    }
}

// ---------------- launch ----------------
extern "C" void kernel_launch(void* const* d_in, const int* in_sizes, int n_in,
                              void* d_out, int out_size)
{
    const float* qw = (const float*)d_in[0];
    const float* kw = (const float*)d_in[1];
    const float* vw = (const float*)d_in[2];
    const float* Wq = (const float*)d_in[3];
    const float* bq = (const float*)d_in[4];
    const float* Wk = (const float*)d_in[5];
    const float* bk = (const float*)d_in[6];
    const float* Wv = (const float*)d_in[7];
    const float* bv = (const float*)d_in[8];
    const float* W1 = (const float*)d_in[9];
    float* out = (float*)d_out;

    float *pq, *pk, *pvt, *penf, *pout2, *ppsum, *ppssq, *pweff;
    cudaGetSymbolAddress((void**)&pq,    g_q);
    cudaGetSymbolAddress((void**)&pk,    g_k);
    cudaGetSymbolAddress((void**)&pvt,   g_vt);
    cudaGetSymbolAddress((void**)&penf,  g_enf);
    cudaGetSymbolAddress((void**)&pout2, g_out2);
    cudaGetSymbolAddress((void**)&ppsum, g_psum);
    cudaGetSymbolAddress((void**)&ppssq, g_pssq);
    cudaGetSymbolAddress((void**)&pweff, g_weff);

    static bool attr_done = false;
    if (!attr_done) {
        cudaFuncSetAttribute(qkv_gemm,      cudaFuncAttributeMaxDynamicSharedMemorySize, 75776);
        cudaFuncSetAttribute(attn_tf32,     cudaFuncAttributeMaxDynamicSharedMemorySize, 104448);
        cudaFuncSetAttribute(dense1_kernel, cudaFuncAttributeMaxDynamicSharedMemorySize, 71680);
        attr_done = true;
    }

    qkv_gemm<<<dim3(8, 64, 3), 256, 75776>>>(qw, kw, vw, Wq, Wk, Wv, bq, bk, bv, pq, pk, pvt);

    attn_tf32<<<dim3(S_ / 128, H_, B_), 256, 104448>>>(pq, pk, pvt, penf, ppsum, ppssq);

    weff_kernel<<<dim3(HF_ / 16, B_), 256>>>(W1, ppsum, ppssq, pweff);

    dense1_kernel<<<dim3((B_ * S_) / 64, 2), 256, 71680>>>(penf, pweff, pout2);

    gnorm_final<<<dim3(F_ / 32, B_), dim3(32, 32)>>>(pout2, out);
}